// round 1
// baseline (speedup 1.0000x reference)
#include <cuda_runtime.h>

// Problem constants (fixed shapes from setup_inputs)
static constexpr int kB  = 8;
static constexpr int kLC = 2048;
static constexpr int kLQ = 1024;
static constexpr int kD  = 768;
static constexpr float kScale = 0.036084391824351615f; // 1/sqrt(768)

// Scratch (no device allocs allowed -> __device__ globals)
__device__ float g_query[(size_t)kB * kLQ * kD];    // 25 MB
__device__ float g_scores[(size_t)kB * kLC * kLQ];  // 64 MB

// ---------------------------------------------------------------------------
// NT GEMM: C[m,n] = scale * sum_k A[m,k] * B[n,k]  (+ bias[n])
// Both operands K-major (row-major with K contiguous). 64x64 tile, BK=16,
// 16x16 threads, 4x4 microtile. Batched via blockIdx.z with strides.
// M,N multiple of 64; K multiple of 16. No bounds checks (exact shapes).
// ---------------------------------------------------------------------------
__global__ void gemm_nt(const float* __restrict__ A, long sA,
                        const float* __restrict__ Bm, long sB,
                        float* __restrict__ C, long sC, int ldc,
                        int M, int N, int K, float scale,
                        const float* __restrict__ bias)
{
    const float* Ab = A  + (long)blockIdx.z * sA;
    const float* Bb = Bm + (long)blockIdx.z * sB;
    float*       Cb = C  + (long)blockIdx.z * sC;

    __shared__ float As[64][17];
    __shared__ float Bs[64][17];

    const int tx = threadIdx.x, ty = threadIdx.y;
    const int tid = ty * 16 + tx;
    const int m0 = blockIdx.y * 64;
    const int n0 = blockIdx.x * 64;

    const int lr = tid >> 2;        // 0..63 (tile row to load)
    const int lk = (tid & 3) * 4;   // 0,4,8,12 (k offset, float4)

    float acc[4][4] = {};

    for (int k0 = 0; k0 < K; k0 += 16) {
        float4 av = *reinterpret_cast<const float4*>(Ab + (long)(m0 + lr) * K + k0 + lk);
        As[lr][lk + 0] = av.x; As[lr][lk + 1] = av.y;
        As[lr][lk + 2] = av.z; As[lr][lk + 3] = av.w;
        float4 bv = *reinterpret_cast<const float4*>(Bb + (long)(n0 + lr) * K + k0 + lk);
        Bs[lr][lk + 0] = bv.x; Bs[lr][lk + 1] = bv.y;
        Bs[lr][lk + 2] = bv.z; Bs[lr][lk + 3] = bv.w;
        __syncthreads();

        #pragma unroll
        for (int kk = 0; kk < 16; kk++) {
            float a[4], b[4];
            #pragma unroll
            for (int i = 0; i < 4; i++) a[i] = As[ty * 4 + i][kk];
            #pragma unroll
            for (int j = 0; j < 4; j++) b[j] = Bs[tx * 4 + j][kk];
            #pragma unroll
            for (int i = 0; i < 4; i++)
                #pragma unroll
                for (int j = 0; j < 4; j++)
                    acc[i][j] += a[i] * b[j];
        }
        __syncthreads();
    }

    #pragma unroll
    for (int i = 0; i < 4; i++) {
        const int r = m0 + ty * 4 + i;
        #pragma unroll
        for (int j = 0; j < 4; j++) {
            const int c = n0 + tx * 4 + j;
            float v = acc[i][j] * scale;
            if (bias) v += bias[c];
            Cb[(long)r * ldc + c] = v;
        }
    }
}

// ---------------------------------------------------------------------------
// NN GEMM: C[m, coff+n] = sum_k A[m,k] * B[k,n]
// A row-major [M,K], B row-major [K,N]. 64x64 tile, BK=16.
// ---------------------------------------------------------------------------
__global__ void gemm_nn(const float* __restrict__ A, long sA,
                        const float* __restrict__ Bm, long sB,
                        float* __restrict__ C, long sC, int ldc, int coff,
                        int M, int N, int K)
{
    const float* Ab = A  + (long)blockIdx.z * sA;
    const float* Bb = Bm + (long)blockIdx.z * sB;
    float*       Cb = C  + (long)blockIdx.z * sC;

    __shared__ float As[64][17];
    __shared__ float Bs[16][64];

    const int tx = threadIdx.x, ty = threadIdx.y;
    const int tid = ty * 16 + tx;
    const int m0 = blockIdx.y * 64;
    const int n0 = blockIdx.x * 64;

    const int lr = tid >> 2;         // A: row 0..63
    const int lk = (tid & 3) * 4;    // A: k offset
    const int kr = tid >> 4;         // B: k row 0..15
    const int nc = (tid & 15) * 4;   // B: n offset

    float acc[4][4] = {};

    for (int k0 = 0; k0 < K; k0 += 16) {
        float4 av = *reinterpret_cast<const float4*>(Ab + (long)(m0 + lr) * K + k0 + lk);
        As[lr][lk + 0] = av.x; As[lr][lk + 1] = av.y;
        As[lr][lk + 2] = av.z; As[lr][lk + 3] = av.w;
        float4 bv = *reinterpret_cast<const float4*>(Bb + (long)(k0 + kr) * N + n0 + nc);
        Bs[kr][nc + 0] = bv.x; Bs[kr][nc + 1] = bv.y;
        Bs[kr][nc + 2] = bv.z; Bs[kr][nc + 3] = bv.w;
        __syncthreads();

        #pragma unroll
        for (int kk = 0; kk < 16; kk++) {
            float a[4], b[4];
            #pragma unroll
            for (int i = 0; i < 4; i++) a[i] = As[ty * 4 + i][kk];
            #pragma unroll
            for (int j = 0; j < 4; j++) b[j] = Bs[kk][tx * 4 + j];
            #pragma unroll
            for (int i = 0; i < 4; i++)
                #pragma unroll
                for (int j = 0; j < 4; j++)
                    acc[i][j] += a[i] * b[j];
        }
        __syncthreads();
    }

    #pragma unroll
    for (int i = 0; i < 4; i++) {
        const int r = m0 + ty * 4 + i;
        #pragma unroll
        for (int j = 0; j < 4; j++) {
            const int c = n0 + tx * 4 + j;
            Cb[(long)r * ldc + coff + c] = acc[i][j];
        }
    }
}

// ---------------------------------------------------------------------------
// Masked softmax over the q axis, in place on g_scores.
// One block (256 threads) per (b, c) row of 1024 scores.
// Masked-out entries get probability 0 (identical to -1e30 reference path:
// every row has >=1 valid token, exp(-1e30 - m) underflows to 0).
// ---------------------------------------------------------------------------
__global__ void softmax_mask(float* __restrict__ scores,
                             const int* __restrict__ qmask)
{
    const int row = blockIdx.x;              // 0 .. B*LC-1
    const int b   = row / kLC;
    float* s = scores + (long)row * kLQ;
    const int* m = qmask + (long)b * kLQ;

    const int t = threadIdx.x;               // 256 threads, 4 elems each
    float v[4]; int mk[4];
    float mx = -1e30f;
    #pragma unroll
    for (int i = 0; i < 4; i++) {
        const int q = t + i * 256;
        v[i]  = s[q];
        mk[i] = m[q];
        if (mk[i]) mx = fmaxf(mx, v[i]);
    }

    __shared__ float smax[8];
    __shared__ float ssum[8];

    #pragma unroll
    for (int off = 16; off; off >>= 1)
        mx = fmaxf(mx, __shfl_xor_sync(0xffffffffu, mx, off));
    if ((t & 31) == 0) smax[t >> 5] = mx;
    __syncthreads();
    float bm = -1e30f;
    #pragma unroll
    for (int w = 0; w < 8; w++) bm = fmaxf(bm, smax[w]);

    float e[4];
    float sum = 0.f;
    #pragma unroll
    for (int i = 0; i < 4; i++) {
        e[i] = mk[i] ? __expf(v[i] - bm) : 0.f;
        sum += e[i];
    }
    #pragma unroll
    for (int off = 16; off; off >>= 1)
        sum += __shfl_xor_sync(0xffffffffu, sum, off);
    if ((t & 31) == 0) ssum[t >> 5] = sum;
    __syncthreads();
    float total = 0.f;
    #pragma unroll
    for (int w = 0; w < 8; w++) total += ssum[w];

    const float inv = 1.f / total;
    #pragma unroll
    for (int i = 0; i < 4; i++)
        s[t + i * 256] = e[i] * inv;
}

// ---------------------------------------------------------------------------
// Copy context into the first D columns of the [B, LC, 2D] output (float4).
// ---------------------------------------------------------------------------
__global__ void copy_ctx(const float4* __restrict__ ctx, float4* __restrict__ out)
{
    const int total = kB * kLC * (kD / 4);   // 3,145,728 float4
    const int idx = blockIdx.x * blockDim.x + threadIdx.x;
    if (idx >= total) return;
    const int row = idx / (kD / 4);
    const int col = idx - row * (kD / 4);
    out[(long)row * (2 * kD / 4) + col] = ctx[idx];
}

// ---------------------------------------------------------------------------
extern "C" void kernel_launch(void* const* d_in, const int* in_sizes, int n_in,
                              void* d_out, int out_size)
{
    const float* ctx  = (const float*)d_in[0];
    // d_in[1] = context_mask (unused by forward, parity with reference)
    const float* qh   = (const float*)d_in[2];
    const int*   qm   = (const int*)d_in[3];
    const float* W    = (const float*)d_in[4];
    const float* bias = (const float*)d_in[5];
    float* out = (float*)d_out;
    (void)in_sizes; (void)n_in; (void)out_size;

    float *query = nullptr, *scores = nullptr;
    cudaGetSymbolAddress((void**)&query, g_query);
    cudaGetSymbolAddress((void**)&scores, g_scores);

    dim3 blk(16, 16);

    // K1: query[b,q,e] = sum_d Qh[b,q,d] * W[e,d] + b[e]   (NT, M=8192,N=768,K=768)
    gemm_nt<<<dim3(kD / 64, (kB * kLQ) / 64, 1), blk>>>(
        qh, 0, W, 0, query, 0, kD,
        kB * kLQ, kD, kD, 1.0f, bias);

    // K2: scores[b,c,q] = scale * sum_d ctx[b,c,d] * query[b,q,d]   (batched NT)
    gemm_nt<<<dim3(kLQ / 64, kLC / 64, kB), blk>>>(
        ctx, (long)kLC * kD, query, (long)kLQ * kD,
        scores, (long)kLC * kLQ, kLQ,
        kLC, kLQ, kD, kScale, nullptr);

    // K3: masked softmax over q, in place
    softmax_mask<<<kB * kLC, 256>>>(scores, qm);

    // Copy context into first half of output
    {
        const int total = kB * kLC * (kD / 4);
        copy_ctx<<<(total + 255) / 256, 256>>>((const float4*)ctx, (float4*)out);
    }

    // K4: out[b,c,D+d] = sum_q P[b,c,q] * Qh[b,q,d]   (batched NN)
    gemm_nn<<<dim3(kD / 64, kLC / 64, kB), blk>>>(
        scores, (long)kLC * kLQ, qh, (long)kLQ * kD,
        out, (long)kLC * 2 * kD, 2 * kD, kD,
        kLC, kD, kLQ);
}

// round 3
// speedup vs baseline: 2.4884x; 2.4884x over previous
#include <cuda_runtime.h>
#include <cuda_bf16.h>
#include <cstdint>

// Problem constants (fixed shapes from setup_inputs)
static constexpr int kB  = 8;
static constexpr int kLC = 2048;
static constexpr int kLQ = 1024;
static constexpr int kD  = 768;
static constexpr float kScale = 0.036084391824351615f; // 1/sqrt(768)

// ---------------------------------------------------------------------------
// Scratch (__device__ globals; no allocs allowed)
// ---------------------------------------------------------------------------
__device__ __nv_bfloat16 g_ctx_hi [(size_t)kB * kLC * kD];
__device__ __nv_bfloat16 g_ctx_lo [(size_t)kB * kLC * kD];
__device__ __nv_bfloat16 g_qh_hi  [(size_t)kB * kLQ * kD];
__device__ __nv_bfloat16 g_qh_lo  [(size_t)kB * kLQ * kD];
__device__ __nv_bfloat16 g_qhT_hi [(size_t)kB * kD * kLQ];
__device__ __nv_bfloat16 g_qhT_lo [(size_t)kB * kD * kLQ];
__device__ __nv_bfloat16 g_W_hi   [(size_t)kD * kD];
__device__ __nv_bfloat16 g_W_lo   [(size_t)kD * kD];
__device__ __nv_bfloat16 g_q_hi   [(size_t)kB * kLQ * kD];  // projected query
__device__ __nv_bfloat16 g_q_lo   [(size_t)kB * kLQ * kD];
__device__ float         g_scores [(size_t)kB * kLC * kLQ];
__device__ __nv_bfloat16 g_p_hi   [(size_t)kB * kLC * kLQ]; // probs
__device__ __nv_bfloat16 g_p_lo   [(size_t)kB * kLC * kLQ];

// ---------------------------------------------------------------------------
// PTX helpers — base sm_103 instructions only (NO tcgen05 in this toolchain)
// ---------------------------------------------------------------------------
__device__ __forceinline__ uint32_t smem_u32(const void* p) {
    uint32_t a;
    asm("{ .reg .u64 t; cvta.to.shared.u64 t, %1; cvt.u32.u64 %0, t; }" : "=r"(a) : "l"(p));
    return a;
}
__device__ __forceinline__ void cp16(uint32_t dst, const void* src) {
    asm volatile("cp.async.cg.shared.global [%0], [%1], 16;" :: "r"(dst), "l"(src) : "memory");
}
__device__ __forceinline__ void cp_commit() { asm volatile("cp.async.commit_group;" ::: "memory"); }
template<int N> __device__ __forceinline__ void cp_wait() {
    asm volatile("cp.async.wait_group %0;" :: "n"(N) : "memory");
}
__device__ __forceinline__ void ldm4(uint32_t* r, uint32_t addr) {
    asm volatile("ldmatrix.sync.aligned.m8n8.x4.shared.b16 {%0,%1,%2,%3}, [%4];"
                 : "=r"(r[0]), "=r"(r[1]), "=r"(r[2]), "=r"(r[3]) : "r"(addr));
}
__device__ __forceinline__ void mma_bf16(float* c, const uint32_t* a, uint32_t b0, uint32_t b1) {
    asm volatile("mma.sync.aligned.m16n8k16.row.col.f32.bf16.bf16.f32 "
                 "{%0,%1,%2,%3}, {%4,%5,%6,%7}, {%8,%9}, {%0,%1,%2,%3};"
                 : "+f"(c[0]), "+f"(c[1]), "+f"(c[2]), "+f"(c[3])
                 : "r"(a[0]), "r"(a[1]), "r"(a[2]), "r"(a[3]), "r"(b0), "r"(b1));
}

// ---------------------------------------------------------------------------
// bf16x3 batched NT GEMM on mma.sync: D[m,n] = sum_k A[m,k]*B[n,k]
//   acc += Ahi*Bhi + Ahi*Blo + Alo*Bhi      (fp32 accumulate)
// CTA tile 128x128, BK=32, 4-stage cp.async pipeline, 8 warps (4Mx2N),
// warp tile 32x64 (2 Mtiles x 8 Ntiles of m16n8k16).
// SMEM rows: 64B data + 16B pad (stride 80B) -> conflict-free ldmatrix.
// MODE 0: out = acc + bias[n] -> bf16 hi/lo (Chi/Clo, ldq)
// MODE 1: out = acc * scale -> Cf[row*ldc + coff + col] (fp32)
// ---------------------------------------------------------------------------
static constexpr int ARR_B   = 10240;      // 128 rows * 80B
static constexpr int STAGE_B = 4 * ARR_B;  // Ahi, Alo, Bhi, Blo
static constexpr int NSTAGE  = 4;
static constexpr int SMEM_SZ = NSTAGE * STAGE_B;  // 163840

template<int MODE>
__global__ void __launch_bounds__(256, 1)
gemm_bf16x3(const __nv_bfloat16* __restrict__ Ahi, const __nv_bfloat16* __restrict__ Alo,
            long sA, int lda,
            const __nv_bfloat16* __restrict__ Bhi, const __nv_bfloat16* __restrict__ Blo,
            long sB, int ldb, int Ktot,
            float* __restrict__ Cf, long sC, int ldc, int coff, float scale,
            const float* __restrict__ bias,
            __nv_bfloat16* __restrict__ Chi, __nv_bfloat16* __restrict__ Clo, int ldq)
{
    extern __shared__ __align__(128) char dsm[];
    const uint32_t base = smem_u32(dsm);

    const int tid  = threadIdx.x;
    const int wid  = tid >> 5;
    const int lane = tid & 31;
    const int wm   = wid & 3;          // warp row 0..3  (32 rows each)
    const int wn   = wid >> 2;         // warp col 0..1  (64 cols each)
    const int z    = blockIdx.z;
    const int m0   = blockIdx.y * 128;
    const int n0   = blockIdx.x * 128;

    const __nv_bfloat16* gp[4];
    gp[0] = Ahi + (long)z * sA + (long)m0 * lda;
    gp[1] = Alo + (long)z * sA + (long)m0 * lda;
    gp[2] = Bhi + (long)z * sB + (long)n0 * ldb;
    gp[3] = Blo + (long)z * sB + (long)n0 * ldb;

    const int S = Ktot >> 5;           // BK=32 stages

    auto load_stage = [&](int s) {
        const uint32_t sb = base + (uint32_t)(s & (NSTAGE - 1)) * STAGE_B;
        const int k0 = s << 5;
        #pragma unroll
        for (int p = 0; p < 4; p++) {
            const int ld = (p < 2) ? lda : ldb;
            #pragma unroll
            for (int j = 0; j < 2; j++) {
                const int ci  = tid + j * 256;      // 0..511
                const int row = ci >> 2;            // 0..127
                const int ch  = ci & 3;             // 16B chunk
                cp16(sb + (uint32_t)p * ARR_B + row * 80 + ch * 16,
                     gp[p] + (long)row * ld + k0 + ch * 8);
            }
        }
        cp_commit();
    };

    // ldmatrix per-lane address components
    const int ati = lane >> 3;
    const int a_row = (lane & 7) + (ati & 1) * 8;     // within 16-row mtile
    const int a_col = (ati >> 1) * 16;                // byte offset (k half)
    const uint32_t a_base = (uint32_t)((wm * 32 + a_row) * 80 + a_col);
    const int b_row = (ati >> 1) * 8 + (lane & 7);    // within 16-row ntile pair
    const int b_col = (ati & 1) * 16;
    const uint32_t b_base = (uint32_t)((wn * 64 + b_row) * 80 + b_col);

    float acc[2][8][4];
    #pragma unroll
    for (int mt = 0; mt < 2; mt++)
        #pragma unroll
        for (int nt = 0; nt < 8; nt++)
            #pragma unroll
            for (int r = 0; r < 4; r++) acc[mt][nt][r] = 0.f;

    load_stage(0);
    load_stage(1);
    load_stage(2);

    for (int s = 0; s < S; s++) {
        const int rem = S - 1 - s;
        if (rem >= 2) cp_wait<2>(); else if (rem == 1) cp_wait<1>(); else cp_wait<0>();
        __syncthreads();
        if (s + 3 < S) load_stage(s + 3);

        const uint32_t sb = base + (uint32_t)(s & (NSTAGE - 1)) * STAGE_B;
        #pragma unroll
        for (int ks = 0; ks < 2; ks++) {
            uint32_t ah[2][4], al[2][4];
            #pragma unroll
            for (int mt = 0; mt < 2; mt++) {
                const uint32_t ao = sb + a_base + (uint32_t)(mt * 16 * 80 + ks * 32);
                ldm4(ah[mt], ao);
                ldm4(al[mt], ao + ARR_B);
            }
            uint32_t bh[4][4], bl[4][4];
            #pragma unroll
            for (int np = 0; np < 4; np++) {
                const uint32_t bo = sb + 2 * ARR_B + b_base + (uint32_t)(np * 16 * 80 + ks * 32);
                ldm4(bh[np], bo);
                ldm4(bl[np], bo + ARR_B);
            }
            #pragma unroll
            for (int mt = 0; mt < 2; mt++)
                #pragma unroll
                for (int nt = 0; nt < 8; nt++) {
                    const int np = nt >> 1, ps = (nt & 1) * 2;
                    mma_bf16(acc[mt][nt], ah[mt], bh[np][ps], bh[np][ps + 1]);
                    mma_bf16(acc[mt][nt], ah[mt], bl[np][ps], bl[np][ps + 1]);
                    mma_bf16(acc[mt][nt], al[mt], bh[np][ps], bh[np][ps + 1]);
                }
        }
        __syncthreads();
    }

    // Epilogue: lane (g = lane>>2, t = lane&3) holds D[g][2t],D[g][2t+1],D[g+8][2t],D[g+8][2t+1]
    const int g = lane >> 2, t = lane & 3;
    #pragma unroll
    for (int mt = 0; mt < 2; mt++) {
        const int r0 = m0 + wm * 32 + mt * 16 + g;
        #pragma unroll
        for (int nt = 0; nt < 8; nt++) {
            const int col = n0 + wn * 64 + nt * 8 + 2 * t;
            float v0 = acc[mt][nt][0], v1 = acc[mt][nt][1];
            float v2 = acc[mt][nt][2], v3 = acc[mt][nt][3];
            if (MODE == 1) {
                float* d0 = Cf + (long)z * sC + (long)r0 * ldc + coff + col;
                float* d1 = d0 + (long)8 * ldc;
                *reinterpret_cast<float2*>(d0) = make_float2(v0 * scale, v1 * scale);
                *reinterpret_cast<float2*>(d1) = make_float2(v2 * scale, v3 * scale);
            } else {
                const float2 bv = *reinterpret_cast<const float2*>(bias + col);
                v0 += bv.x; v1 += bv.y; v2 += bv.x; v3 += bv.y;
                __nv_bfloat16 h0 = __float2bfloat16(v0), h1 = __float2bfloat16(v1);
                __nv_bfloat16 h2 = __float2bfloat16(v2), h3 = __float2bfloat16(v3);
                __nv_bfloat162 p0; p0.x = h0; p0.y = h1;
                __nv_bfloat162 p1; p1.x = h2; p1.y = h3;
                __nv_bfloat162 q0; q0.x = __float2bfloat16(v0 - __bfloat162float(h0));
                                   q0.y = __float2bfloat16(v1 - __bfloat162float(h1));
                __nv_bfloat162 q1; q1.x = __float2bfloat16(v2 - __bfloat162float(h2));
                                   q1.y = __float2bfloat16(v3 - __bfloat162float(h3));
                __nv_bfloat16* dh0 = Chi + (long)r0 * ldq + col;
                __nv_bfloat16* dl0 = Clo + (long)r0 * ldq + col;
                *reinterpret_cast<__nv_bfloat162*>(dh0) = p0;
                *reinterpret_cast<__nv_bfloat162*>(dh0 + 8 * ldq) = p1;
                *reinterpret_cast<__nv_bfloat162*>(dl0) = q0;
                *reinterpret_cast<__nv_bfloat162*>(dl0 + 8 * ldq) = q1;
            }
        }
    }
}

// ---------------------------------------------------------------------------
// fp32 -> bf16 hi/lo split (elementwise, float4)
// ---------------------------------------------------------------------------
__global__ void split_fp32(const float* __restrict__ in,
                           __nv_bfloat16* __restrict__ hi,
                           __nv_bfloat16* __restrict__ lo, int n4)
{
    const int i = blockIdx.x * blockDim.x + threadIdx.x;
    if (i >= n4) return;
    const float4 v = reinterpret_cast<const float4*>(in)[i];
    const float f[4] = {v.x, v.y, v.z, v.w};
    __nv_bfloat162 ph[2], pl[2];
    #pragma unroll
    for (int j = 0; j < 2; j++) {
        __nv_bfloat16 h0 = __float2bfloat16(f[2*j+0]);
        __nv_bfloat16 h1 = __float2bfloat16(f[2*j+1]);
        ph[j].x = h0; ph[j].y = h1;
        pl[j].x = __float2bfloat16(f[2*j+0] - __bfloat162float(h0));
        pl[j].y = __float2bfloat16(f[2*j+1] - __bfloat162float(h1));
    }
    reinterpret_cast<__nv_bfloat162*>(hi)[2*i+0] = ph[0];
    reinterpret_cast<__nv_bfloat162*>(hi)[2*i+1] = ph[1];
    reinterpret_cast<__nv_bfloat162*>(lo)[2*i+0] = pl[0];
    reinterpret_cast<__nv_bfloat162*>(lo)[2*i+1] = pl[1];
}

// ---------------------------------------------------------------------------
// qh [B, LQ, D] -> qhT hi/lo [B, D, LQ]  (32x32 smem tile transpose + split)
// ---------------------------------------------------------------------------
__global__ void transpose_split(const float* __restrict__ in,
                                __nv_bfloat16* __restrict__ oh,
                                __nv_bfloat16* __restrict__ ol)
{
    __shared__ float t[32][33];
    const int b  = blockIdx.z;
    const int d0 = blockIdx.x * 32;
    const int q0 = blockIdx.y * 32;
    const int tx = threadIdx.x, ty = threadIdx.y;
    const float* ib = in + (long)b * kLQ * kD;
    #pragma unroll
    for (int j = 0; j < 4; j++)
        t[ty + 8 * j][tx] = ib[(long)(q0 + ty + 8 * j) * kD + d0 + tx];
    __syncthreads();
    __nv_bfloat16* bh = oh + (long)b * kD * kLQ;
    __nv_bfloat16* bl = ol + (long)b * kD * kLQ;
    #pragma unroll
    for (int j = 0; j < 4; j++) {
        const float v = t[tx][ty + 8 * j];
        const __nv_bfloat16 h = __float2bfloat16(v);
        const long o = (long)(d0 + ty + 8 * j) * kLQ + q0 + tx;
        bh[o] = h;
        bl[o] = __float2bfloat16(v - __bfloat162float(h));
    }
}

// ---------------------------------------------------------------------------
// Masked softmax over q; reads fp32 scores, writes bf16 hi/lo probs.
// ---------------------------------------------------------------------------
__global__ void softmax_mask(const float* __restrict__ scores,
                             const int* __restrict__ qmask,
                             __nv_bfloat16* __restrict__ phi,
                             __nv_bfloat16* __restrict__ plo)
{
    const int row = blockIdx.x;              // 0 .. B*LC-1
    const int b   = row / kLC;
    const float* s = scores + (long)row * kLQ;
    const int*   m = qmask + (long)b * kLQ;

    const int t = threadIdx.x;               // 256 threads, 4 elems each
    float v[4]; int mk[4];
    float mx = -1e30f;
    #pragma unroll
    for (int i = 0; i < 4; i++) {
        const int q = t + i * 256;
        v[i]  = s[q];
        mk[i] = m[q];
        if (mk[i]) mx = fmaxf(mx, v[i]);
    }

    __shared__ float smax[8];
    __shared__ float ssum[8];

    #pragma unroll
    for (int off = 16; off; off >>= 1)
        mx = fmaxf(mx, __shfl_xor_sync(0xffffffffu, mx, off));
    if ((t & 31) == 0) smax[t >> 5] = mx;
    __syncthreads();
    float bm = -1e30f;
    #pragma unroll
    for (int w = 0; w < 8; w++) bm = fmaxf(bm, smax[w]);

    float e[4];
    float sum = 0.f;
    #pragma unroll
    for (int i = 0; i < 4; i++) {
        e[i] = mk[i] ? __expf(v[i] - bm) : 0.f;
        sum += e[i];
    }
    #pragma unroll
    for (int off = 16; off; off >>= 1)
        sum += __shfl_xor_sync(0xffffffffu, sum, off);
    if ((t & 31) == 0) ssum[t >> 5] = sum;
    __syncthreads();
    float total = 0.f;
    #pragma unroll
    for (int w = 0; w < 8; w++) total += ssum[w];

    const float inv = 1.f / total;
    __nv_bfloat16* dh = phi + (long)row * kLQ;
    __nv_bfloat16* dl = plo + (long)row * kLQ;
    #pragma unroll
    for (int i = 0; i < 4; i++) {
        const int q = t + i * 256;
        const float p = e[i] * inv;
        const __nv_bfloat16 h = __float2bfloat16(p);
        dh[q] = h;
        dl[q] = __float2bfloat16(p - __bfloat162float(h));
    }
}

// ---------------------------------------------------------------------------
// Copy context into first D columns of [B, LC, 2D] output.
// ---------------------------------------------------------------------------
__global__ void copy_ctx(const float4* __restrict__ ctx, float4* __restrict__ out)
{
    const int total = kB * kLC * (kD / 4);
    const int idx = blockIdx.x * blockDim.x + threadIdx.x;
    if (idx >= total) return;
    const int row = idx / (kD / 4);
    const int col = idx - row * (kD / 4);
    out[(long)row * (2 * kD / 4) + col] = ctx[idx];
}

// ---------------------------------------------------------------------------
extern "C" void kernel_launch(void* const* d_in, const int* in_sizes, int n_in,
                              void* d_out, int out_size)
{
    const float* ctx  = (const float*)d_in[0];
    const float* qh   = (const float*)d_in[2];
    const int*   qm   = (const int*)d_in[3];
    const float* W    = (const float*)d_in[4];
    const float* bias = (const float*)d_in[5];
    float* out = (float*)d_out;
    (void)in_sizes; (void)n_in; (void)out_size;

    __nv_bfloat16 *ctx_hi, *ctx_lo, *qh_hi, *qh_lo, *qhT_hi, *qhT_lo;
    __nv_bfloat16 *W_hi, *W_lo, *q_hi, *q_lo, *p_hi, *p_lo;
    float* scores;
    cudaGetSymbolAddress((void**)&ctx_hi, g_ctx_hi);
    cudaGetSymbolAddress((void**)&ctx_lo, g_ctx_lo);
    cudaGetSymbolAddress((void**)&qh_hi,  g_qh_hi);
    cudaGetSymbolAddress((void**)&qh_lo,  g_qh_lo);
    cudaGetSymbolAddress((void**)&qhT_hi, g_qhT_hi);
    cudaGetSymbolAddress((void**)&qhT_lo, g_qhT_lo);
    cudaGetSymbolAddress((void**)&W_hi,   g_W_hi);
    cudaGetSymbolAddress((void**)&W_lo,   g_W_lo);
    cudaGetSymbolAddress((void**)&q_hi,   g_q_hi);
    cudaGetSymbolAddress((void**)&q_lo,   g_q_lo);
    cudaGetSymbolAddress((void**)&p_hi,   g_p_hi);
    cudaGetSymbolAddress((void**)&p_lo,   g_p_lo);
    cudaGetSymbolAddress((void**)&scores, g_scores);

    cudaFuncSetAttribute(gemm_bf16x3<0>, cudaFuncAttributeMaxDynamicSharedMemorySize, SMEM_SZ);
    cudaFuncSetAttribute(gemm_bf16x3<1>, cudaFuncAttributeMaxDynamicSharedMemorySize, SMEM_SZ);

    // --- conversions ---
    split_fp32<<<(kB * kLC * kD / 4 + 255) / 256, 256>>>(ctx, ctx_hi, ctx_lo, kB * kLC * kD / 4);
    split_fp32<<<(kB * kLQ * kD / 4 + 255) / 256, 256>>>(qh, qh_hi, qh_lo, kB * kLQ * kD / 4);
    split_fp32<<<(kD * kD / 4 + 255) / 256, 256>>>(W, W_hi, W_lo, kD * kD / 4);
    transpose_split<<<dim3(kD / 32, kLQ / 32, kB), dim3(32, 8)>>>(qh, qhT_hi, qhT_lo);

    // --- K1: query = qh @ W^T + b -> bf16 hi/lo  (M=8192, N=768, K=768) ---
    gemm_bf16x3<0><<<dim3(kD / 128, (kB * kLQ) / 128, 1), 256, SMEM_SZ>>>(
        qh_hi, qh_lo, 0, kD,
        W_hi, W_lo, 0, kD, kD,
        nullptr, 0, 0, 0, 1.0f, bias,
        q_hi, q_lo, kD);

    // --- K2: scores = scale * ctx @ query^T  (batched; M=2048, N=1024, K=768) ---
    gemm_bf16x3<1><<<dim3(kLQ / 128, kLC / 128, kB), 256, SMEM_SZ>>>(
        ctx_hi, ctx_lo, (long)kLC * kD, kD,
        q_hi, q_lo, (long)kLQ * kD, kD, kD,
        scores, (long)kLC * kLQ, kLQ, 0, kScale, nullptr,
        nullptr, nullptr, 0);

    // --- K3: masked softmax -> bf16 hi/lo probs ---
    softmax_mask<<<kB * kLC, 256>>>(scores, qm, p_hi, p_lo);

    // --- copy context into first half of output ---
    copy_ctx<<<(kB * kLC * (kD / 4) + 255) / 256, 256>>>((const float4*)ctx, (float4*)out);

    // --- K4: out[:, D:] = probs @ qhT^T  (batched; M=2048, N=768, K=1024) ---
    gemm_bf16x3<1><<<dim3(kD / 128, kLC / 128, kB), 256, SMEM_SZ>>>(
        p_hi, p_lo, (long)kLC * kLQ, kLQ,
        qhT_hi, qhT_lo, (long)kD * kLQ, kLQ, kLQ,
        out, (long)kLC * 2 * kD, 2 * kD, kD, 1.0f, nullptr,
        nullptr, nullptr, 0);
}

// round 5
// speedup vs baseline: 4.0984x; 1.6470x over previous
#include <cuda_runtime.h>
#include <cuda_bf16.h>
#include <cstdint>

// Problem constants (fixed shapes from setup_inputs)
static constexpr int kB  = 8;
static constexpr int kLC = 2048;
static constexpr int kLQ = 1024;
static constexpr int kD  = 768;
static constexpr float kScale = 0.036084391824351615f; // 1/sqrt(768)

// ---------------------------------------------------------------------------
// Scratch (__device__ globals; no allocs allowed)
// ---------------------------------------------------------------------------
__device__ __nv_bfloat16 g_ctx_hi [(size_t)kB * kLC * kD];
__device__ __nv_bfloat16 g_ctx_lo [(size_t)kB * kLC * kD];
__device__ __nv_bfloat16 g_qh_hi  [(size_t)kB * kLQ * kD];
__device__ __nv_bfloat16 g_qh_lo  [(size_t)kB * kLQ * kD];
__device__ __nv_bfloat16 g_qhT_hi [(size_t)kB * kD * kLQ];   // PACKED columns
__device__ __nv_bfloat16 g_qhT_lo [(size_t)kB * kD * kLQ];   // PACKED columns
__device__ __nv_bfloat16 g_W_hi   [(size_t)kD * kD];
__device__ __nv_bfloat16 g_W_lo   [(size_t)kD * kD];
__device__ __nv_bfloat16 g_q_hi   [(size_t)kB * kLQ * kD];   // projected query
__device__ __nv_bfloat16 g_q_lo   [(size_t)kB * kLQ * kD];
__device__ float         g_scores [(size_t)kB * kLC * kLQ];  // packed cols
__device__ __nv_bfloat16 g_p_hi   [(size_t)kB * kLC * kLQ];  // packed probs
__device__ int           g_qvalid [kB * kLQ];                // packed->orig q
__device__ int           g_rank   [kB * kLQ];                // orig q->packed (-1 invalid)
__device__ int           g_Lv     [kB];                      // valid count per batch

// ---------------------------------------------------------------------------
// PTX helpers — base sm_103 instructions only (NO tcgen05 in this toolchain)
// ---------------------------------------------------------------------------
__device__ __forceinline__ uint32_t smem_u32(const void* p) {
    uint32_t a;
    asm("{ .reg .u64 t; cvta.to.shared.u64 t, %1; cvt.u32.u64 %0, t; }" : "=r"(a) : "l"(p));
    return a;
}
__device__ __forceinline__ void cp16(uint32_t dst, const void* src) {
    asm volatile("cp.async.cg.shared.global [%0], [%1], 16;" :: "r"(dst), "l"(src) : "memory");
}
__device__ __forceinline__ void cp_commit() { asm volatile("cp.async.commit_group;" ::: "memory"); }
template<int N> __device__ __forceinline__ void cp_wait() {
    asm volatile("cp.async.wait_group %0;" :: "n"(N) : "memory");
}
__device__ __forceinline__ void ldm4(uint32_t* r, uint32_t addr) {
    asm volatile("ldmatrix.sync.aligned.m8n8.x4.shared.b16 {%0,%1,%2,%3}, [%4];"
                 : "=r"(r[0]), "=r"(r[1]), "=r"(r[2]), "=r"(r[3]) : "r"(addr));
}
__device__ __forceinline__ void mma_bf16(float* c, const uint32_t* a, uint32_t b0, uint32_t b1) {
    asm volatile("mma.sync.aligned.m16n8k16.row.col.f32.bf16.bf16.f32 "
                 "{%0,%1,%2,%3}, {%4,%5,%6,%7}, {%8,%9}, {%0,%1,%2,%3};"
                 : "+f"(c[0]), "+f"(c[1]), "+f"(c[2]), "+f"(c[3])
                 : "r"(a[0]), "r"(a[1]), "r"(a[2]), "r"(a[3]), "r"(b0), "r"(b1));
}

// ---------------------------------------------------------------------------
// Tensor-core NT GEMM, bf16 multi-term with fp32 accumulate.
// CTA tile 128x128, BK=32, 4-stage cp.async pipeline, 8 warps (4Mx2N).
// MODE 0 (K1): 3 terms (AhBh+AhBl+AlBh); +bias; out -> bf16 hi/lo (query)
// MODE 1 (K2): 3 terms; B rows gathered via qvalid; exit if n0>=Lv[z];
//              out = acc*scale -> fp32 scores (packed cols)
// MODE 2 (K4): 2 terms (AhBh+AhBl), A=p_hi only; runtime K=pad128(Lv[z]);
//              out = acc -> fp32 at out[.. , coff + col]
// ---------------------------------------------------------------------------
static constexpr int ARR_B   = 10240;      // 128 rows * 80B (64B data + 16B pad)
static constexpr int STAGE_B = 4 * ARR_B;
static constexpr int NSTAGE  = 4;
static constexpr int SMEM_SZ = NSTAGE * STAGE_B;  // 163840

template<int MODE>
__global__ void __launch_bounds__(256, 1)
gemm_tc(const __nv_bfloat16* __restrict__ Ahi, const __nv_bfloat16* __restrict__ Alo,
        long sA, int lda,
        const __nv_bfloat16* __restrict__ Bhi, const __nv_bfloat16* __restrict__ Blo,
        long sB, int ldb, int Kstatic,
        float* __restrict__ Cf, long sC, int ldc, int coff, float scale,
        const float* __restrict__ bias,
        __nv_bfloat16* __restrict__ Chi, __nv_bfloat16* __restrict__ Clo, int ldq,
        const int* __restrict__ qvalid, const int* __restrict__ LvArr)
{
    constexpr bool NT3 = (MODE != 2);   // use A_lo term
    constexpr bool GAT = (MODE == 1);   // gather B rows

    const int z  = blockIdx.z;
    const int m0 = blockIdx.y * 128;
    const int n0 = blockIdx.x * 128;

    int lv = 0;
    if (MODE == 1 || MODE == 2) lv = __ldg(&LvArr[z]);
    if (GAT && n0 >= lv) return;        // uniform per CTA

    int Ktot = Kstatic;
    if (MODE == 2) Ktot = (lv + 127) & ~127;

    extern __shared__ __align__(128) char dsm[];
    const uint32_t base = smem_u32(dsm);
    __shared__ int s_qidx[128];

    const int tid  = threadIdx.x;
    const int wid  = tid >> 5;
    const int lane = tid & 31;
    const int wm   = wid & 3;
    const int wn   = wid >> 2;

    const __nv_bfloat16* pAh = Ahi + (long)z * sA + (long)m0 * lda;
    const __nv_bfloat16* pAl = NT3 ? (Alo + (long)z * sA + (long)m0 * lda) : pAh;
    const __nv_bfloat16* pBh = Bhi + (long)z * sB;
    const __nv_bfloat16* pBl = Blo + (long)z * sB;

    int qr0 = n0 + (tid >> 2), qr1 = n0 + (tid >> 2) + 64;
    if (GAT) {
        if (tid < 128) {
            const int qi = n0 + tid;
            s_qidx[tid] = (qi < lv) ? __ldg(&qvalid[z * kLQ + qi]) : 0;
        }
        __syncthreads();
        qr0 = s_qidx[tid >> 2];
        qr1 = s_qidx[(tid >> 2) + 64];
    }

    const int S = Ktot >> 5;           // BK=32 stages (>=4 always)

    auto load_stage = [&](int s) {
        const uint32_t sb = base + (uint32_t)(s & (NSTAGE - 1)) * STAGE_B;
        const int k0 = s << 5;
        const int r  = tid >> 2;
        const int ch = tid & 3;
        // A hi (+ lo)
        cp16(sb + 0 * ARR_B + r * 80 + ch * 16,        pAh + (long)r * lda + k0 + ch * 8);
        cp16(sb + 0 * ARR_B + (r + 64) * 80 + ch * 16, pAh + (long)(r + 64) * lda + k0 + ch * 8);
        if (NT3) {
            cp16(sb + 1 * ARR_B + r * 80 + ch * 16,        pAl + (long)r * lda + k0 + ch * 8);
            cp16(sb + 1 * ARR_B + (r + 64) * 80 + ch * 16, pAl + (long)(r + 64) * lda + k0 + ch * 8);
        }
        // B hi / lo (row offset n0 folded into qr* for non-gather)
        const long b0 = (long)qr0 * ldb + k0 + ch * 8;
        const long b1 = (long)qr1 * ldb + k0 + ch * 8;
        cp16(sb + 2 * ARR_B + r * 80 + ch * 16,        pBh + b0);
        cp16(sb + 2 * ARR_B + (r + 64) * 80 + ch * 16, pBh + b1);
        cp16(sb + 3 * ARR_B + r * 80 + ch * 16,        pBl + b0);
        cp16(sb + 3 * ARR_B + (r + 64) * 80 + ch * 16, pBl + b1);
        cp_commit();
    };

    // ldmatrix per-lane address components
    const int ati = lane >> 3;
    const int a_row = (lane & 7) + (ati & 1) * 8;
    const int a_col = (ati >> 1) * 16;
    const uint32_t a_base = (uint32_t)((wm * 32 + a_row) * 80 + a_col);
    const int b_row = (ati >> 1) * 8 + (lane & 7);
    const int b_col = (ati & 1) * 16;
    const uint32_t b_base = (uint32_t)((wn * 64 + b_row) * 80 + b_col);

    float acc[2][8][4];
    #pragma unroll
    for (int mt = 0; mt < 2; mt++)
        #pragma unroll
        for (int nt = 0; nt < 8; nt++)
            #pragma unroll
            for (int r = 0; r < 4; r++) acc[mt][nt][r] = 0.f;

    load_stage(0);
    load_stage(1);
    load_stage(2);

    for (int s = 0; s < S; s++) {
        const int rem = S - 1 - s;
        if (rem >= 2) cp_wait<2>(); else if (rem == 1) cp_wait<1>(); else cp_wait<0>();
        __syncthreads();
        if (s + 3 < S) load_stage(s + 3);

        const uint32_t sb = base + (uint32_t)(s & (NSTAGE - 1)) * STAGE_B;
        #pragma unroll
        for (int ks = 0; ks < 2; ks++) {
            uint32_t ah[2][4], al[2][4];
            #pragma unroll
            for (int mt = 0; mt < 2; mt++) {
                const uint32_t ao = sb + a_base + (uint32_t)(mt * 16 * 80 + ks * 32);
                ldm4(ah[mt], ao);
                if (NT3) ldm4(al[mt], ao + ARR_B);
            }
            uint32_t bh[4][4], bl[4][4];
            #pragma unroll
            for (int np = 0; np < 4; np++) {
                const uint32_t bo = sb + 2 * ARR_B + b_base + (uint32_t)(np * 16 * 80 + ks * 32);
                ldm4(bh[np], bo);
                ldm4(bl[np], bo + ARR_B);
            }
            #pragma unroll
            for (int mt = 0; mt < 2; mt++)
                #pragma unroll
                for (int nt = 0; nt < 8; nt++) {
                    const int np = nt >> 1, ps = (nt & 1) * 2;
                    mma_bf16(acc[mt][nt], ah[mt], bh[np][ps], bh[np][ps + 1]);
                    mma_bf16(acc[mt][nt], ah[mt], bl[np][ps], bl[np][ps + 1]);
                    if (NT3) mma_bf16(acc[mt][nt], al[mt], bh[np][ps], bh[np][ps + 1]);
                }
        }
        __syncthreads();
    }

    // Epilogue
    const int g = lane >> 2, t = lane & 3;
    #pragma unroll
    for (int mt = 0; mt < 2; mt++) {
        const int r0 = m0 + wm * 32 + mt * 16 + g;
        #pragma unroll
        for (int nt = 0; nt < 8; nt++) {
            const int col = n0 + wn * 64 + nt * 8 + 2 * t;
            float v0 = acc[mt][nt][0], v1 = acc[mt][nt][1];
            float v2 = acc[mt][nt][2], v3 = acc[mt][nt][3];
            if (MODE != 0) {
                float* d0 = Cf + (long)z * sC + (long)r0 * ldc + coff + col;
                float* d1 = d0 + (long)8 * ldc;
                *reinterpret_cast<float2*>(d0) = make_float2(v0 * scale, v1 * scale);
                *reinterpret_cast<float2*>(d1) = make_float2(v2 * scale, v3 * scale);
            } else {
                const float2 bv = *reinterpret_cast<const float2*>(bias + col);
                v0 += bv.x; v1 += bv.y; v2 += bv.x; v3 += bv.y;
                __nv_bfloat16 h0 = __float2bfloat16(v0), h1 = __float2bfloat16(v1);
                __nv_bfloat16 h2 = __float2bfloat16(v2), h3 = __float2bfloat16(v3);
                __nv_bfloat162 p0; p0.x = h0; p0.y = h1;
                __nv_bfloat162 p1; p1.x = h2; p1.y = h3;
                __nv_bfloat162 q0; q0.x = __float2bfloat16(v0 - __bfloat162float(h0));
                                   q0.y = __float2bfloat16(v1 - __bfloat162float(h1));
                __nv_bfloat162 q1; q1.x = __float2bfloat16(v2 - __bfloat162float(h2));
                                   q1.y = __float2bfloat16(v3 - __bfloat162float(h3));
                __nv_bfloat16* dh0 = Chi + (long)r0 * ldq + col;
                __nv_bfloat16* dl0 = Clo + (long)r0 * ldq + col;
                *reinterpret_cast<__nv_bfloat162*>(dh0) = p0;
                *reinterpret_cast<__nv_bfloat162*>(dh0 + 8 * ldq) = p1;
                *reinterpret_cast<__nv_bfloat162*>(dl0) = q0;
                *reinterpret_cast<__nv_bfloat162*>(dl0 + 8 * ldq) = q1;
            }
        }
    }
}

// ---------------------------------------------------------------------------
// Per-batch mask prefix scan: qvalid (packed->orig), rank (orig->packed), Lv.
// One block of 256 threads per batch; each thread owns 4 consecutive q.
// ---------------------------------------------------------------------------
__global__ void mask_scan(const int* __restrict__ qm,
                          int* __restrict__ qvalid, int* __restrict__ rank,
                          int* __restrict__ Lv)
{
    const int b = blockIdx.x, t = threadIdx.x;
    __shared__ int sc[256];
    const int* m = qm + (long)b * kLQ;
    int mv[4];
    #pragma unroll
    for (int i = 0; i < 4; i++) mv[i] = m[t * 4 + i];
    const int c = mv[0] + mv[1] + mv[2] + mv[3];
    sc[t] = c;
    __syncthreads();
    for (int off = 1; off < 256; off <<= 1) {
        const int v = (t >= off) ? sc[t - off] : 0;
        __syncthreads();
        sc[t] += v;
        __syncthreads();
    }
    int exc = sc[t] - c;
    int* qv = qvalid + (long)b * kLQ;
    int* rk = rank   + (long)b * kLQ;
    #pragma unroll
    for (int i = 0; i < 4; i++) {
        const int q = t * 4 + i;
        if (mv[i]) { rk[q] = exc; qv[exc] = q; exc++; }
        else       { rk[q] = -1; }
    }
    if (t == 255) Lv[b] = sc[255];
}

// ---------------------------------------------------------------------------
// ctx: one read -> output first half copy + bf16 hi/lo split
// ---------------------------------------------------------------------------
__global__ void prep_ctx(const float* __restrict__ ctx, float* __restrict__ out,
                         __nv_bfloat16* __restrict__ hi, __nv_bfloat16* __restrict__ lo)
{
    const int n4 = kB * kLC * (kD / 4);
    const int i = blockIdx.x * blockDim.x + threadIdx.x;
    if (i >= n4) return;
    const float4 v = reinterpret_cast<const float4*>(ctx)[i];
    const int row = i / (kD / 4);
    const int col = i - row * (kD / 4);
    reinterpret_cast<float4*>(out)[(long)row * (2 * kD / 4) + col] = v;
    const float f[4] = {v.x, v.y, v.z, v.w};
    #pragma unroll
    for (int j = 0; j < 2; j++) {
        __nv_bfloat16 h0 = __float2bfloat16(f[2*j+0]);
        __nv_bfloat16 h1 = __float2bfloat16(f[2*j+1]);
        __nv_bfloat162 ph; ph.x = h0; ph.y = h1;
        __nv_bfloat162 pl;
        pl.x = __float2bfloat16(f[2*j+0] - __bfloat162float(h0));
        pl.y = __float2bfloat16(f[2*j+1] - __bfloat162float(h1));
        reinterpret_cast<__nv_bfloat162*>(hi)[2*i+j] = ph;
        reinterpret_cast<__nv_bfloat162*>(lo)[2*i+j] = pl;
    }
}

// ---------------------------------------------------------------------------
// fp32 -> bf16 hi/lo split (elementwise, float4)
// ---------------------------------------------------------------------------
__global__ void split_fp32(const float* __restrict__ in,
                           __nv_bfloat16* __restrict__ hi,
                           __nv_bfloat16* __restrict__ lo, int n4)
{
    const int i = blockIdx.x * blockDim.x + threadIdx.x;
    if (i >= n4) return;
    const float4 v = reinterpret_cast<const float4*>(in)[i];
    const float f[4] = {v.x, v.y, v.z, v.w};
    #pragma unroll
    for (int j = 0; j < 2; j++) {
        __nv_bfloat16 h0 = __float2bfloat16(f[2*j+0]);
        __nv_bfloat16 h1 = __float2bfloat16(f[2*j+1]);
        __nv_bfloat162 ph; ph.x = h0; ph.y = h1;
        __nv_bfloat162 pl;
        pl.x = __float2bfloat16(f[2*j+0] - __bfloat162float(h0));
        pl.y = __float2bfloat16(f[2*j+1] - __bfloat162float(h1));
        reinterpret_cast<__nv_bfloat162*>(hi)[2*i+j] = ph;
        reinterpret_cast<__nv_bfloat162*>(lo)[2*i+j] = pl;
    }
}

// ---------------------------------------------------------------------------
// qh [B,LQ,D] -> packed transposed qhT hi/lo [B,D,packed_q]
// 32x32 smem tile; only valid q columns written, at their packed rank.
// Pad columns (>= Lv) are never written: p there is 0, so any value is fine.
// ---------------------------------------------------------------------------
__global__ void transpose_pack(const float* __restrict__ in,
                               const int* __restrict__ rank,
                               __nv_bfloat16* __restrict__ oh,
                               __nv_bfloat16* __restrict__ ol)
{
    __shared__ float t[32][33];
    __shared__ int rk[32];
    const int b  = blockIdx.z;
    const int d0 = blockIdx.x * 32;
    const int q0 = blockIdx.y * 32;
    const int tx = threadIdx.x, ty = threadIdx.y;
    const float* ib = in + (long)b * kLQ * kD;
    #pragma unroll
    for (int j = 0; j < 4; j++)
        t[ty + 8 * j][tx] = ib[(long)(q0 + ty + 8 * j) * kD + d0 + tx];
    if (ty == 0) rk[tx] = rank[(long)b * kLQ + q0 + tx];
    __syncthreads();
    const int col = rk[tx];
    if (col < 0) return;
    __nv_bfloat16* bh = oh + (long)b * kD * kLQ;
    __nv_bfloat16* bl = ol + (long)b * kD * kLQ;
    #pragma unroll
    for (int j = 0; j < 4; j++) {
        const float v = t[tx][ty + 8 * j];
        const __nv_bfloat16 h = __float2bfloat16(v);
        const long o = (long)(d0 + ty + 8 * j) * kLQ + col;
        bh[o] = h;
        bl[o] = __float2bfloat16(v - __bfloat162float(h));
    }
}

// ---------------------------------------------------------------------------
// Softmax over packed columns [0, Lv); writes p_hi with zeros for j >= Lv.
// ---------------------------------------------------------------------------
__global__ void softmax_packed(const float* __restrict__ scores,
                               const int* __restrict__ LvArr,
                               __nv_bfloat16* __restrict__ phi)
{
    const int row = blockIdx.x;              // 0 .. B*LC-1
    const int b   = row >> 11;               // / kLC
    const int lv  = __ldg(&LvArr[b]);
    const float* s = scores + (long)row * kLQ;

    const int t = threadIdx.x;               // 256 threads, 4 elems each
    float v[4]; int ok[4];
    float mx = -1e30f;
    #pragma unroll
    for (int i = 0; i < 4; i++) {
        const int q = t + i * 256;
        ok[i] = (q < lv);
        v[i]  = ok[i] ? s[q] : 0.f;
        if (ok[i]) mx = fmaxf(mx, v[i]);
    }

    __shared__ float smax[8];
    __shared__ float ssum[8];

    #pragma unroll
    for (int off = 16; off; off >>= 1)
        mx = fmaxf(mx, __shfl_xor_sync(0xffffffffu, mx, off));
    if ((t & 31) == 0) smax[t >> 5] = mx;
    __syncthreads();
    float bm = -1e30f;
    #pragma unroll
    for (int w = 0; w < 8; w++) bm = fmaxf(bm, smax[w]);

    float e[4];
    float sum = 0.f;
    #pragma unroll
    for (int i = 0; i < 4; i++) {
        e[i] = ok[i] ? __expf(v[i] - bm) : 0.f;
        sum += e[i];
    }
    #pragma unroll
    for (int off = 16; off; off >>= 1)
        sum += __shfl_xor_sync(0xffffffffu, sum, off);
    if ((t & 31) == 0) ssum[t >> 5] = sum;
    __syncthreads();
    float total = 0.f;
    #pragma unroll
    for (int w = 0; w < 8; w++) total += ssum[w];

    const float inv = 1.f / total;
    __nv_bfloat16* dh = phi + (long)row * kLQ;
    #pragma unroll
    for (int i = 0; i < 4; i++) {
        const int q = t + i * 256;
        dh[q] = __float2bfloat16(e[i] * inv);   // 0 for q >= lv
    }
}

// ---------------------------------------------------------------------------
extern "C" void kernel_launch(void* const* d_in, const int* in_sizes, int n_in,
                              void* d_out, int out_size)
{
    const float* ctx  = (const float*)d_in[0];
    const float* qh   = (const float*)d_in[2];
    const int*   qm   = (const int*)d_in[3];
    const float* W    = (const float*)d_in[4];
    const float* bias = (const float*)d_in[5];
    float* out = (float*)d_out;
    (void)in_sizes; (void)n_in; (void)out_size;

    __nv_bfloat16 *ctx_hi, *ctx_lo, *qh_hi, *qh_lo, *qhT_hi, *qhT_lo;
    __nv_bfloat16 *W_hi, *W_lo, *q_hi, *q_lo, *p_hi;
    float* scores;
    int *qvalid, *rank, *Lv;
    cudaGetSymbolAddress((void**)&ctx_hi, g_ctx_hi);
    cudaGetSymbolAddress((void**)&ctx_lo, g_ctx_lo);
    cudaGetSymbolAddress((void**)&qh_hi,  g_qh_hi);
    cudaGetSymbolAddress((void**)&qh_lo,  g_qh_lo);
    cudaGetSymbolAddress((void**)&qhT_hi, g_qhT_hi);
    cudaGetSymbolAddress((void**)&qhT_lo, g_qhT_lo);
    cudaGetSymbolAddress((void**)&W_hi,   g_W_hi);
    cudaGetSymbolAddress((void**)&W_lo,   g_W_lo);
    cudaGetSymbolAddress((void**)&q_hi,   g_q_hi);
    cudaGetSymbolAddress((void**)&q_lo,   g_q_lo);
    cudaGetSymbolAddress((void**)&p_hi,   g_p_hi);
    cudaGetSymbolAddress((void**)&scores, g_scores);
    cudaGetSymbolAddress((void**)&qvalid, g_qvalid);
    cudaGetSymbolAddress((void**)&rank,   g_rank);
    cudaGetSymbolAddress((void**)&Lv,     g_Lv);

    cudaFuncSetAttribute(gemm_tc<0>, cudaFuncAttributeMaxDynamicSharedMemorySize, SMEM_SZ);
    cudaFuncSetAttribute(gemm_tc<1>, cudaFuncAttributeMaxDynamicSharedMemorySize, SMEM_SZ);
    cudaFuncSetAttribute(gemm_tc<2>, cudaFuncAttributeMaxDynamicSharedMemorySize, SMEM_SZ);

    // --- prep ---
    prep_ctx<<<(kB * kLC * (kD / 4) + 255) / 256, 256>>>(ctx, out, ctx_hi, ctx_lo);
    split_fp32<<<(kB * kLQ * kD / 4 + 255) / 256, 256>>>(qh, qh_hi, qh_lo, kB * kLQ * kD / 4);
    split_fp32<<<(kD * kD / 4 + 255) / 256, 256>>>(W, W_hi, W_lo, kD * kD / 4);
    mask_scan<<<kB, 256>>>(qm, qvalid, rank, Lv);
    transpose_pack<<<dim3(kD / 32, kLQ / 32, kB), dim3(32, 8)>>>(qh, rank, qhT_hi, qhT_lo);

    // --- K1: query = qh @ W^T + b -> bf16 hi/lo (M=8192, N=768, K=768, 3 terms) ---
    gemm_tc<0><<<dim3(kD / 128, (kB * kLQ) / 128, 1), 256, SMEM_SZ>>>(
        qh_hi, qh_lo, 0, kD,
        W_hi, W_lo, 0, kD, kD,
        nullptr, 0, 0, 0, 1.0f, bias,
        q_hi, q_lo, kD, nullptr, nullptr);

    // --- K2: packed scores = scale * ctx @ query[qvalid]^T (3 terms, gather) ---
    gemm_tc<1><<<dim3(kLQ / 128, kLC / 128, kB), 256, SMEM_SZ>>>(
        ctx_hi, ctx_lo, (long)kLC * kD, kD,
        q_hi, q_lo, (long)kLQ * kD, kD, kD,
        scores, (long)kLC * kLQ, kLQ, 0, kScale, nullptr,
        nullptr, nullptr, 0, qvalid, Lv);

    // --- K3: softmax over packed columns -> p_hi (zeros beyond Lv) ---
    softmax_packed<<<kB * kLC, 256>>>(scores, Lv, p_hi);

    // --- K4: out[:, D:] = p_hi @ qhT_packed^T (2 terms, runtime K = pad128(Lv)) ---
    gemm_tc<2><<<dim3(kD / 128, kLC / 128, kB), 256, SMEM_SZ>>>(
        p_hi, nullptr, (long)kLC * kLQ, kLQ,
        qhT_hi, qhT_lo, (long)kD * kLQ, kLQ, 0,
        out, (long)kLC * 2 * kD, 2 * kD, kD, 1.0f, nullptr,
        nullptr, nullptr, 0, nullptr, Lv);
}

// round 6
// speedup vs baseline: 4.8250x; 1.1773x over previous
#include <cuda_runtime.h>
#include <cuda_bf16.h>
#include <cstdint>

// Problem constants (fixed shapes from setup_inputs)
static constexpr int kB  = 8;
static constexpr int kLC = 2048;
static constexpr int kLQ = 1024;
static constexpr int kD  = 768;
static constexpr float kScale = 0.036084391824351615f; // 1/sqrt(768)

// ---------------------------------------------------------------------------
// Scratch (__device__ globals; no allocs allowed)
// "lo" residual arrays exist only for B-side operands: W, query, qhT.
// ---------------------------------------------------------------------------
__device__ __nv_bfloat16 g_ctx_hi [(size_t)kB * kLC * kD];
__device__ __nv_bfloat16 g_qh_hi  [(size_t)kB * kLQ * kD];
__device__ __nv_bfloat16 g_qhT_hi [(size_t)kB * kD * kLQ];   // PACKED columns
__device__ __nv_bfloat16 g_qhT_lo [(size_t)kB * kD * kLQ];   // PACKED columns
__device__ __nv_bfloat16 g_W_hi   [(size_t)kD * kD];
__device__ __nv_bfloat16 g_W_lo   [(size_t)kD * kD];
__device__ __nv_bfloat16 g_q_hi   [(size_t)kB * kLQ * kD];   // projected query
__device__ __nv_bfloat16 g_q_lo   [(size_t)kB * kLQ * kD];
__device__ float         g_scores [(size_t)kB * kLC * kLQ];  // packed cols
__device__ __nv_bfloat16 g_p_hi   [(size_t)kB * kLC * kLQ];  // packed probs
__device__ int           g_qvalid [kB * kLQ];                // packed->orig q
__device__ int           g_rank   [kB * kLQ];                // orig q->packed (-1 invalid)
__device__ int           g_Lv     [kB];                      // valid count per batch

// ---------------------------------------------------------------------------
// PTX helpers — base sm_103 instructions only (NO tcgen05 in this toolchain)
// ---------------------------------------------------------------------------
__device__ __forceinline__ uint32_t smem_u32(const void* p) {
    uint32_t a;
    asm("{ .reg .u64 t; cvta.to.shared.u64 t, %1; cvt.u32.u64 %0, t; }" : "=r"(a) : "l"(p));
    return a;
}
__device__ __forceinline__ void cp16(uint32_t dst, const void* src) {
    asm volatile("cp.async.cg.shared.global [%0], [%1], 16;" :: "r"(dst), "l"(src) : "memory");
}
__device__ __forceinline__ void cp_commit() { asm volatile("cp.async.commit_group;" ::: "memory"); }
template<int N> __device__ __forceinline__ void cp_wait() {
    asm volatile("cp.async.wait_group %0;" :: "n"(N) : "memory");
}
__device__ __forceinline__ void ldm4(uint32_t* r, uint32_t addr) {
    asm volatile("ldmatrix.sync.aligned.m8n8.x4.shared.b16 {%0,%1,%2,%3}, [%4];"
                 : "=r"(r[0]), "=r"(r[1]), "=r"(r[2]), "=r"(r[3]) : "r"(addr));
}
__device__ __forceinline__ void mma_bf16(float* c, const uint32_t* a, uint32_t b0, uint32_t b1) {
    asm volatile("mma.sync.aligned.m16n8k16.row.col.f32.bf16.bf16.f32 "
                 "{%0,%1,%2,%3}, {%4,%5,%6,%7}, {%8,%9}, {%0,%1,%2,%3};"
                 : "+f"(c[0]), "+f"(c[1]), "+f"(c[2]), "+f"(c[3])
                 : "r"(a[0]), "r"(a[1]), "r"(a[2]), "r"(a[3]), "r"(b0), "r"(b1));
}

// ---------------------------------------------------------------------------
// Tensor-core NT GEMM, 2-term bf16 with fp32 accumulate:
//   acc = A_hi*B_hi + A_hi*B_lo
// CTA tile 128x128, BK=32, 4-stage cp.async pipeline (3 arrays/stage),
// 8 warps (4Mx2N), warp tile 32x64.
// MODE 0 (K1): +bias; out -> bf16 hi/lo (query)
// MODE 1 (K2): B rows gathered via qvalid; exit if n0>=Lv[z]; out=acc*scale fp32
// MODE 2 (K4): runtime K=pad128(Lv[z]); out=acc fp32 at [.., coff+col]
// ---------------------------------------------------------------------------
static constexpr int ARR_B   = 10240;      // 128 rows * 80B (64B data + 16B pad)
static constexpr int STAGE_B = 3 * ARR_B;  // A, Bhi, Blo
static constexpr int NSTAGE  = 4;
static constexpr int SMEM_SZ = NSTAGE * STAGE_B;  // 122880

template<int MODE>
__global__ void __launch_bounds__(256, 1)
gemm_tc(const __nv_bfloat16* __restrict__ Ahi, long sA, int lda,
        const __nv_bfloat16* __restrict__ Bhi, const __nv_bfloat16* __restrict__ Blo,
        long sB, int ldb, int Kstatic,
        float* __restrict__ Cf, long sC, int ldc, int coff, float scale,
        const float* __restrict__ bias,
        __nv_bfloat16* __restrict__ Chi, __nv_bfloat16* __restrict__ Clo, int ldq,
        const int* __restrict__ qvalid, const int* __restrict__ LvArr)
{
    constexpr bool GAT = (MODE == 1);   // gather B rows

    const int z  = blockIdx.z;
    const int m0 = blockIdx.y * 128;
    const int n0 = blockIdx.x * 128;

    int lv = 0;
    if (MODE == 1 || MODE == 2) lv = __ldg(&LvArr[z]);
    if (GAT && n0 >= lv) return;        // uniform per CTA

    int Ktot = Kstatic;
    if (MODE == 2) Ktot = (lv + 127) & ~127;

    extern __shared__ __align__(128) char dsm[];
    const uint32_t base = smem_u32(dsm);
    __shared__ int s_qidx[128];

    const int tid  = threadIdx.x;
    const int wid  = tid >> 5;
    const int lane = tid & 31;
    const int wm   = wid & 3;
    const int wn   = wid >> 2;

    const __nv_bfloat16* pAh = Ahi + (long)z * sA + (long)m0 * lda;
    const __nv_bfloat16* pBh = Bhi + (long)z * sB;
    const __nv_bfloat16* pBl = Blo + (long)z * sB;

    int qr0 = n0 + (tid >> 2), qr1 = n0 + (tid >> 2) + 64;
    if (GAT) {
        if (tid < 128) {
            const int qi = n0 + tid;
            s_qidx[tid] = (qi < lv) ? __ldg(&qvalid[z * kLQ + qi]) : 0;
        }
        __syncthreads();
        qr0 = s_qidx[tid >> 2];
        qr1 = s_qidx[(tid >> 2) + 64];
    }

    const int S = Ktot >> 5;           // BK=32 stages (>=4 always)

    auto load_stage = [&](int s) {
        const uint32_t sb = base + (uint32_t)(s & (NSTAGE - 1)) * STAGE_B;
        const int k0 = s << 5;
        const int r  = tid >> 2;
        const int ch = tid & 3;
        cp16(sb + r * 80 + ch * 16,        pAh + (long)r * lda + k0 + ch * 8);
        cp16(sb + (r + 64) * 80 + ch * 16, pAh + (long)(r + 64) * lda + k0 + ch * 8);
        const long b0 = (long)qr0 * ldb + k0 + ch * 8;
        const long b1 = (long)qr1 * ldb + k0 + ch * 8;
        cp16(sb + 1 * ARR_B + r * 80 + ch * 16,        pBh + b0);
        cp16(sb + 1 * ARR_B + (r + 64) * 80 + ch * 16, pBh + b1);
        cp16(sb + 2 * ARR_B + r * 80 + ch * 16,        pBl + b0);
        cp16(sb + 2 * ARR_B + (r + 64) * 80 + ch * 16, pBl + b1);
        cp_commit();
    };

    // ldmatrix per-lane address components
    const int ati = lane >> 3;
    const int a_row = (lane & 7) + (ati & 1) * 8;
    const int a_col = (ati >> 1) * 16;
    const uint32_t a_base = (uint32_t)((wm * 32 + a_row) * 80 + a_col);
    const int b_row = (ati >> 1) * 8 + (lane & 7);
    const int b_col = (ati & 1) * 16;
    const uint32_t b_base = (uint32_t)((wn * 64 + b_row) * 80 + b_col);

    float acc[2][8][4];
    #pragma unroll
    for (int mt = 0; mt < 2; mt++)
        #pragma unroll
        for (int nt = 0; nt < 8; nt++)
            #pragma unroll
            for (int r = 0; r < 4; r++) acc[mt][nt][r] = 0.f;

    load_stage(0);
    load_stage(1);
    load_stage(2);

    for (int s = 0; s < S; s++) {
        const int rem = S - 1 - s;
        if (rem >= 2) cp_wait<2>(); else if (rem == 1) cp_wait<1>(); else cp_wait<0>();
        __syncthreads();
        if (s + 3 < S) load_stage(s + 3);

        const uint32_t sb = base + (uint32_t)(s & (NSTAGE - 1)) * STAGE_B;
        #pragma unroll
        for (int ks = 0; ks < 2; ks++) {
            uint32_t ah[2][4];
            #pragma unroll
            for (int mt = 0; mt < 2; mt++)
                ldm4(ah[mt], sb + a_base + (uint32_t)(mt * 16 * 80 + ks * 32));
            uint32_t bh[4][4], bl[4][4];
            #pragma unroll
            for (int np = 0; np < 4; np++) {
                const uint32_t bo = sb + 1 * ARR_B + b_base + (uint32_t)(np * 16 * 80 + ks * 32);
                ldm4(bh[np], bo);
                ldm4(bl[np], bo + ARR_B);
            }
            #pragma unroll
            for (int mt = 0; mt < 2; mt++)
                #pragma unroll
                for (int nt = 0; nt < 8; nt++) {
                    const int np = nt >> 1, ps = (nt & 1) * 2;
                    mma_bf16(acc[mt][nt], ah[mt], bh[np][ps], bh[np][ps + 1]);
                    mma_bf16(acc[mt][nt], ah[mt], bl[np][ps], bl[np][ps + 1]);
                }
        }
        __syncthreads();
    }

    // Epilogue
    const int g = lane >> 2, t = lane & 3;
    #pragma unroll
    for (int mt = 0; mt < 2; mt++) {
        const int r0 = m0 + wm * 32 + mt * 16 + g;
        #pragma unroll
        for (int nt = 0; nt < 8; nt++) {
            const int col = n0 + wn * 64 + nt * 8 + 2 * t;
            float v0 = acc[mt][nt][0], v1 = acc[mt][nt][1];
            float v2 = acc[mt][nt][2], v3 = acc[mt][nt][3];
            if (MODE != 0) {
                float* d0 = Cf + (long)z * sC + (long)r0 * ldc + coff + col;
                float* d1 = d0 + (long)8 * ldc;
                *reinterpret_cast<float2*>(d0) = make_float2(v0 * scale, v1 * scale);
                *reinterpret_cast<float2*>(d1) = make_float2(v2 * scale, v3 * scale);
            } else {
                const float2 bv = *reinterpret_cast<const float2*>(bias + col);
                v0 += bv.x; v1 += bv.y; v2 += bv.x; v3 += bv.y;
                __nv_bfloat16 h0 = __float2bfloat16(v0), h1 = __float2bfloat16(v1);
                __nv_bfloat16 h2 = __float2bfloat16(v2), h3 = __float2bfloat16(v3);
                __nv_bfloat162 p0; p0.x = h0; p0.y = h1;
                __nv_bfloat162 p1; p1.x = h2; p1.y = h3;
                __nv_bfloat162 q0; q0.x = __float2bfloat16(v0 - __bfloat162float(h0));
                                   q0.y = __float2bfloat16(v1 - __bfloat162float(h1));
                __nv_bfloat162 q1; q1.x = __float2bfloat16(v2 - __bfloat162float(h2));
                                   q1.y = __float2bfloat16(v3 - __bfloat162float(h3));
                __nv_bfloat16* dh0 = Chi + (long)r0 * ldq + col;
                __nv_bfloat16* dl0 = Clo + (long)r0 * ldq + col;
                *reinterpret_cast<__nv_bfloat162*>(dh0) = p0;
                *reinterpret_cast<__nv_bfloat162*>(dh0 + 8 * ldq) = p1;
                *reinterpret_cast<__nv_bfloat162*>(dl0) = q0;
                *reinterpret_cast<__nv_bfloat162*>(dl0 + 8 * ldq) = q1;
            }
        }
    }
}

// ---------------------------------------------------------------------------
// Per-batch mask prefix scan: qvalid (packed->orig), rank (orig->packed), Lv.
// ---------------------------------------------------------------------------
__global__ void mask_scan(const int* __restrict__ qm,
                          int* __restrict__ qvalid, int* __restrict__ rank,
                          int* __restrict__ Lv)
{
    const int b = blockIdx.x, t = threadIdx.x;
    __shared__ int sc[256];
    const int* m = qm + (long)b * kLQ;
    int mv[4];
    #pragma unroll
    for (int i = 0; i < 4; i++) mv[i] = m[t * 4 + i];
    const int c = mv[0] + mv[1] + mv[2] + mv[3];
    sc[t] = c;
    __syncthreads();
    for (int off = 1; off < 256; off <<= 1) {
        const int v = (t >= off) ? sc[t - off] : 0;
        __syncthreads();
        sc[t] += v;
        __syncthreads();
    }
    int exc = sc[t] - c;
    int* qv = qvalid + (long)b * kLQ;
    int* rk = rank   + (long)b * kLQ;
    #pragma unroll
    for (int i = 0; i < 4; i++) {
        const int q = t * 4 + i;
        if (mv[i]) { rk[q] = exc; qv[exc] = q; exc++; }
        else       { rk[q] = -1; }
    }
    if (t == 255) Lv[b] = sc[255];
}

// ---------------------------------------------------------------------------
// ctx: one read -> output first half copy + bf16 hi split (no lo needed)
// ---------------------------------------------------------------------------
__global__ void prep_ctx(const float* __restrict__ ctx, float* __restrict__ out,
                         __nv_bfloat16* __restrict__ hi)
{
    const int n4 = kB * kLC * (kD / 4);
    const int i = blockIdx.x * blockDim.x + threadIdx.x;
    if (i >= n4) return;
    const float4 v = reinterpret_cast<const float4*>(ctx)[i];
    const int row = i / (kD / 4);
    const int col = i - row * (kD / 4);
    reinterpret_cast<float4*>(out)[(long)row * (2 * kD / 4) + col] = v;
    __nv_bfloat162 p0; p0.x = __float2bfloat16(v.x); p0.y = __float2bfloat16(v.y);
    __nv_bfloat162 p1; p1.x = __float2bfloat16(v.z); p1.y = __float2bfloat16(v.w);
    reinterpret_cast<__nv_bfloat162*>(hi)[2*i+0] = p0;
    reinterpret_cast<__nv_bfloat162*>(hi)[2*i+1] = p1;
}

// ---------------------------------------------------------------------------
// fp32 -> bf16 hi only (qh)
// ---------------------------------------------------------------------------
__global__ void split_hi(const float* __restrict__ in,
                         __nv_bfloat16* __restrict__ hi, int n4)
{
    const int i = blockIdx.x * blockDim.x + threadIdx.x;
    if (i >= n4) return;
    const float4 v = reinterpret_cast<const float4*>(in)[i];
    __nv_bfloat162 p0; p0.x = __float2bfloat16(v.x); p0.y = __float2bfloat16(v.y);
    __nv_bfloat162 p1; p1.x = __float2bfloat16(v.z); p1.y = __float2bfloat16(v.w);
    reinterpret_cast<__nv_bfloat162*>(hi)[2*i+0] = p0;
    reinterpret_cast<__nv_bfloat162*>(hi)[2*i+1] = p1;
}

// ---------------------------------------------------------------------------
// fp32 -> bf16 hi/lo split (W)
// ---------------------------------------------------------------------------
__global__ void split_hilo(const float* __restrict__ in,
                           __nv_bfloat16* __restrict__ hi,
                           __nv_bfloat16* __restrict__ lo, int n4)
{
    const int i = blockIdx.x * blockDim.x + threadIdx.x;
    if (i >= n4) return;
    const float4 v = reinterpret_cast<const float4*>(in)[i];
    const float f[4] = {v.x, v.y, v.z, v.w};
    #pragma unroll
    for (int j = 0; j < 2; j++) {
        __nv_bfloat16 h0 = __float2bfloat16(f[2*j+0]);
        __nv_bfloat16 h1 = __float2bfloat16(f[2*j+1]);
        __nv_bfloat162 ph; ph.x = h0; ph.y = h1;
        __nv_bfloat162 pl;
        pl.x = __float2bfloat16(f[2*j+0] - __bfloat162float(h0));
        pl.y = __float2bfloat16(f[2*j+1] - __bfloat162float(h1));
        reinterpret_cast<__nv_bfloat162*>(hi)[2*i+j] = ph;
        reinterpret_cast<__nv_bfloat162*>(lo)[2*i+j] = pl;
    }
}

// ---------------------------------------------------------------------------
// qh [B,LQ,D] -> packed transposed qhT hi/lo [B,D,packed_q]
// ---------------------------------------------------------------------------
__global__ void transpose_pack(const float* __restrict__ in,
                               const int* __restrict__ rank,
                               __nv_bfloat16* __restrict__ oh,
                               __nv_bfloat16* __restrict__ ol)
{
    __shared__ float t[32][33];
    __shared__ int rk[32];
    const int b  = blockIdx.z;
    const int d0 = blockIdx.x * 32;
    const int q0 = blockIdx.y * 32;
    const int tx = threadIdx.x, ty = threadIdx.y;
    const float* ib = in + (long)b * kLQ * kD;
    #pragma unroll
    for (int j = 0; j < 4; j++)
        t[ty + 8 * j][tx] = ib[(long)(q0 + ty + 8 * j) * kD + d0 + tx];
    if (ty == 0) rk[tx] = rank[(long)b * kLQ + q0 + tx];
    __syncthreads();
    const int col = rk[tx];
    if (col < 0) return;
    __nv_bfloat16* bh = oh + (long)b * kD * kLQ;
    __nv_bfloat16* bl = ol + (long)b * kD * kLQ;
    #pragma unroll
    for (int j = 0; j < 4; j++) {
        const float v = t[tx][ty + 8 * j];
        const __nv_bfloat16 h = __float2bfloat16(v);
        const long o = (long)(d0 + ty + 8 * j) * kLQ + col;
        bh[o] = h;
        bl[o] = __float2bfloat16(v - __bfloat162float(h));
    }
}

// ---------------------------------------------------------------------------
// Softmax over packed columns [0, Lv); writes p_hi with zeros for j >= Lv.
// ---------------------------------------------------------------------------
__global__ void softmax_packed(const float* __restrict__ scores,
                               const int* __restrict__ LvArr,
                               __nv_bfloat16* __restrict__ phi)
{
    const int row = blockIdx.x;              // 0 .. B*LC-1
    const int b   = row >> 11;               // / kLC
    const int lv  = __ldg(&LvArr[b]);
    const float* s = scores + (long)row * kLQ;

    const int t = threadIdx.x;               // 256 threads, 4 elems each
    float v[4]; int ok[4];
    float mx = -1e30f;
    #pragma unroll
    for (int i = 0; i < 4; i++) {
        const int q = t + i * 256;
        ok[i] = (q < lv);
        v[i]  = ok[i] ? s[q] : 0.f;
        if (ok[i]) mx = fmaxf(mx, v[i]);
    }

    __shared__ float smax[8];
    __shared__ float ssum[8];

    #pragma unroll
    for (int off = 16; off; off >>= 1)
        mx = fmaxf(mx, __shfl_xor_sync(0xffffffffu, mx, off));
    if ((t & 31) == 0) smax[t >> 5] = mx;
    __syncthreads();
    float bm = -1e30f;
    #pragma unroll
    for (int w = 0; w < 8; w++) bm = fmaxf(bm, smax[w]);

    float e[4];
    float sum = 0.f;
    #pragma unroll
    for (int i = 0; i < 4; i++) {
        e[i] = ok[i] ? __expf(v[i] - bm) : 0.f;
        sum += e[i];
    }
    #pragma unroll
    for (int off = 16; off; off >>= 1)
        sum += __shfl_xor_sync(0xffffffffu, sum, off);
    if ((t & 31) == 0) ssum[t >> 5] = sum;
    __syncthreads();
    float total = 0.f;
    #pragma unroll
    for (int w = 0; w < 8; w++) total += ssum[w];

    const float inv = 1.f / total;
    __nv_bfloat16* dh = phi + (long)row * kLQ;
    #pragma unroll
    for (int i = 0; i < 4; i++) {
        const int q = t + i * 256;
        dh[q] = __float2bfloat16(e[i] * inv);   // 0 for q >= lv
    }
}

// ---------------------------------------------------------------------------
extern "C" void kernel_launch(void* const* d_in, const int* in_sizes, int n_in,
                              void* d_out, int out_size)
{
    const float* ctx  = (const float*)d_in[0];
    const float* qh   = (const float*)d_in[2];
    const int*   qm   = (const int*)d_in[3];
    const float* W    = (const float*)d_in[4];
    const float* bias = (const float*)d_in[5];
    float* out = (float*)d_out;
    (void)in_sizes; (void)n_in; (void)out_size;

    __nv_bfloat16 *ctx_hi, *qh_hi, *qhT_hi, *qhT_lo;
    __nv_bfloat16 *W_hi, *W_lo, *q_hi, *q_lo, *p_hi;
    float* scores;
    int *qvalid, *rank, *Lv;
    cudaGetSymbolAddress((void**)&ctx_hi, g_ctx_hi);
    cudaGetSymbolAddress((void**)&qh_hi,  g_qh_hi);
    cudaGetSymbolAddress((void**)&qhT_hi, g_qhT_hi);
    cudaGetSymbolAddress((void**)&qhT_lo, g_qhT_lo);
    cudaGetSymbolAddress((void**)&W_hi,   g_W_hi);
    cudaGetSymbolAddress((void**)&W_lo,   g_W_lo);
    cudaGetSymbolAddress((void**)&q_hi,   g_q_hi);
    cudaGetSymbolAddress((void**)&q_lo,   g_q_lo);
    cudaGetSymbolAddress((void**)&p_hi,   g_p_hi);
    cudaGetSymbolAddress((void**)&scores, g_scores);
    cudaGetSymbolAddress((void**)&qvalid, g_qvalid);
    cudaGetSymbolAddress((void**)&rank,   g_rank);
    cudaGetSymbolAddress((void**)&Lv,     g_Lv);

    cudaFuncSetAttribute(gemm_tc<0>, cudaFuncAttributeMaxDynamicSharedMemorySize, SMEM_SZ);
    cudaFuncSetAttribute(gemm_tc<1>, cudaFuncAttributeMaxDynamicSharedMemorySize, SMEM_SZ);
    cudaFuncSetAttribute(gemm_tc<2>, cudaFuncAttributeMaxDynamicSharedMemorySize, SMEM_SZ);

    // --- prep ---
    prep_ctx<<<(kB * kLC * (kD / 4) + 255) / 256, 256>>>(ctx, out, ctx_hi);
    split_hi<<<(kB * kLQ * kD / 4 + 255) / 256, 256>>>(qh, qh_hi, kB * kLQ * kD / 4);
    split_hilo<<<(kD * kD / 4 + 255) / 256, 256>>>(W, W_hi, W_lo, kD * kD / 4);
    mask_scan<<<kB, 256>>>(qm, qvalid, rank, Lv);
    transpose_pack<<<dim3(kD / 32, kLQ / 32, kB), dim3(32, 8)>>>(qh, rank, qhT_hi, qhT_lo);

    // --- K1: query = qh_hi @ (W_hi + W_lo)^T + b -> bf16 hi/lo ---
    gemm_tc<0><<<dim3(kD / 128, (kB * kLQ) / 128, 1), 256, SMEM_SZ>>>(
        qh_hi, 0, kD,
        W_hi, W_lo, 0, kD, kD,
        nullptr, 0, 0, 0, 1.0f, bias,
        q_hi, q_lo, kD, nullptr, nullptr);

    // --- K2: packed scores = scale * ctx_hi @ (q_hi + q_lo)[qvalid]^T ---
    gemm_tc<1><<<dim3(kLQ / 128, kLC / 128, kB), 256, SMEM_SZ>>>(
        ctx_hi, (long)kLC * kD, kD,
        q_hi, q_lo, (long)kLQ * kD, kD, kD,
        scores, (long)kLC * kLQ, kLQ, 0, kScale, nullptr,
        nullptr, nullptr, 0, qvalid, Lv);

    // --- K3: softmax over packed columns -> p_hi (zeros beyond Lv) ---
    softmax_packed<<<kB * kLC, 256>>>(scores, Lv, p_hi);

    // --- K4: out[:, D:] = p_hi @ (qhT_hi + qhT_lo)^T (runtime K = pad128(Lv)) ---
    gemm_tc<2><<<dim3(kD / 128, kLC / 128, kB), 256, SMEM_SZ>>>(
        p_hi, (long)kLC * kLQ, kLQ,
        qhT_hi, qhT_lo, (long)kD * kLQ, kLQ, 0,
        out, (long)kLC * 2 * kD, 2 * kD, kD, 1.0f, nullptr,
        nullptr, nullptr, 0, nullptr, Lv);
}

// round 7
// speedup vs baseline: 8.2082x; 1.7012x over previous
#include <cuda_runtime.h>
#include <cuda_bf16.h>
#include <cstdint>

// Problem constants (fixed shapes from setup_inputs)
static constexpr int kB  = 8;
static constexpr int kLC = 2048;
static constexpr int kLQ = 1024;
static constexpr int kD  = 768;
static constexpr float kScale = 0.036084391824351615f; // 1/sqrt(768)

// ---------------------------------------------------------------------------
// Scratch (__device__ globals; no allocs allowed) — pure bf16 pipeline
// ---------------------------------------------------------------------------
__device__ __nv_bfloat16 g_ctx_hi [(size_t)kB * kLC * kD];
__device__ __nv_bfloat16 g_qh_hi  [(size_t)kB * kLQ * kD];
__device__ __nv_bfloat16 g_qhT_hi [(size_t)kB * kD * kLQ];   // PACKED columns
__device__ __nv_bfloat16 g_W_hi   [(size_t)kD * kD];
__device__ __nv_bfloat16 g_q_hi   [(size_t)kB * kLQ * kD];   // projected query
__device__ float         g_scores [(size_t)kB * kLC * kLQ];  // packed cols
__device__ __nv_bfloat16 g_p_hi   [(size_t)kB * kLC * kLQ];  // packed probs
__device__ int           g_qvalid [kB * kLQ];                // packed->orig q
__device__ int           g_rank   [kB * kLQ];                // orig q->packed (-1 invalid)
__device__ int           g_Lv     [kB];                      // valid count per batch

// ---------------------------------------------------------------------------
// PTX helpers — base sm_103 instructions only (NO tcgen05 in this toolchain)
// ---------------------------------------------------------------------------
__device__ __forceinline__ uint32_t smem_u32(const void* p) {
    uint32_t a;
    asm("{ .reg .u64 t; cvta.to.shared.u64 t, %1; cvt.u32.u64 %0, t; }" : "=r"(a) : "l"(p));
    return a;
}
__device__ __forceinline__ void cp16(uint32_t dst, const void* src) {
    asm volatile("cp.async.cg.shared.global [%0], [%1], 16;" :: "r"(dst), "l"(src) : "memory");
}
__device__ __forceinline__ void cp_commit() { asm volatile("cp.async.commit_group;" ::: "memory"); }
template<int N> __device__ __forceinline__ void cp_wait() {
    asm volatile("cp.async.wait_group %0;" :: "n"(N) : "memory");
}
__device__ __forceinline__ void ldm4(uint32_t* r, uint32_t addr) {
    asm volatile("ldmatrix.sync.aligned.m8n8.x4.shared.b16 {%0,%1,%2,%3}, [%4];"
                 : "=r"(r[0]), "=r"(r[1]), "=r"(r[2]), "=r"(r[3]) : "r"(addr));
}
__device__ __forceinline__ void mma_bf16(float* c, const uint32_t* a, uint32_t b0, uint32_t b1) {
    asm volatile("mma.sync.aligned.m16n8k16.row.col.f32.bf16.bf16.f32 "
                 "{%0,%1,%2,%3}, {%4,%5,%6,%7}, {%8,%9}, {%0,%1,%2,%3};"
                 : "+f"(c[0]), "+f"(c[1]), "+f"(c[2]), "+f"(c[3])
                 : "r"(a[0]), "r"(a[1]), "r"(a[2]), "r"(a[3]), "r"(b0), "r"(b1));
}

// ---------------------------------------------------------------------------
// Tensor-core NT GEMM, single-term bf16 with fp32 accumulate: acc = A*B^T
// CTA tile 128x128, BK=32, 4-stage cp.async pipeline (2 arrays/stage = 80KB),
// 8 warps (4Mx2N), warp tile 32x64, 2 CTAs/SM.
// MODE 0 (K1): +bias; out -> bf16 (query)
// MODE 1 (K2): B rows gathered via qvalid; exit if n0>=Lv[z]; out=acc*scale fp32
// MODE 2 (K4): runtime K=pad128(Lv[z]); out=acc fp32 at [.., coff+col]
// ---------------------------------------------------------------------------
static constexpr int ARR_B   = 10240;      // 128 rows * 80B (64B data + 16B pad)
static constexpr int STAGE_B = 2 * ARR_B;  // A, B
static constexpr int NSTAGE  = 4;
static constexpr int SMEM_SZ = NSTAGE * STAGE_B;  // 81920

template<int MODE>
__global__ void __launch_bounds__(256, 2)
gemm_tc(const __nv_bfloat16* __restrict__ Ahi, long sA, int lda,
        const __nv_bfloat16* __restrict__ Bhi, long sB, int ldb, int Kstatic,
        float* __restrict__ Cf, long sC, int ldc, int coff, float scale,
        const float* __restrict__ bias,
        __nv_bfloat16* __restrict__ Chi, int ldq,
        const int* __restrict__ qvalid, const int* __restrict__ LvArr)
{
    constexpr bool GAT = (MODE == 1);   // gather B rows

    const int z  = blockIdx.z;
    const int m0 = blockIdx.y * 128;
    const int n0 = blockIdx.x * 128;

    int lv = 0;
    if (MODE == 1 || MODE == 2) lv = __ldg(&LvArr[z]);
    if (GAT && n0 >= lv) return;        // uniform per CTA

    int Ktot = Kstatic;
    if (MODE == 2) Ktot = (lv + 127) & ~127;

    extern __shared__ __align__(128) char dsm[];
    const uint32_t base = smem_u32(dsm);
    __shared__ int s_qidx[128];

    const int tid  = threadIdx.x;
    const int wid  = tid >> 5;
    const int lane = tid & 31;
    const int wm   = wid & 3;
    const int wn   = wid >> 2;

    const __nv_bfloat16* pAh = Ahi + (long)z * sA + (long)m0 * lda;
    const __nv_bfloat16* pBh = Bhi + (long)z * sB;

    int qr0 = n0 + (tid >> 2), qr1 = n0 + (tid >> 2) + 64;
    if (GAT) {
        if (tid < 128) {
            const int qi = n0 + tid;
            s_qidx[tid] = (qi < lv) ? __ldg(&qvalid[z * kLQ + qi]) : 0;
        }
        __syncthreads();
        qr0 = s_qidx[tid >> 2];
        qr1 = s_qidx[(tid >> 2) + 64];
    }

    const int S = Ktot >> 5;           // BK=32 stages (>=4 always)

    auto load_stage = [&](int s) {
        const uint32_t sb = base + (uint32_t)(s & (NSTAGE - 1)) * STAGE_B;
        const int k0 = s << 5;
        const int r  = tid >> 2;
        const int ch = tid & 3;
        cp16(sb + r * 80 + ch * 16,        pAh + (long)r * lda + k0 + ch * 8);
        cp16(sb + (r + 64) * 80 + ch * 16, pAh + (long)(r + 64) * lda + k0 + ch * 8);
        cp16(sb + ARR_B + r * 80 + ch * 16,        pBh + (long)qr0 * ldb + k0 + ch * 8);
        cp16(sb + ARR_B + (r + 64) * 80 + ch * 16, pBh + (long)qr1 * ldb + k0 + ch * 8);
        cp_commit();
    };

    // ldmatrix per-lane address components
    const int ati = lane >> 3;
    const int a_row = (lane & 7) + (ati & 1) * 8;
    const int a_col = (ati >> 1) * 16;
    const uint32_t a_base = (uint32_t)((wm * 32 + a_row) * 80 + a_col);
    const int b_row = (ati >> 1) * 8 + (lane & 7);
    const int b_col = (ati & 1) * 16;
    const uint32_t b_base = (uint32_t)((wn * 64 + b_row) * 80 + b_col);

    float acc[2][8][4];
    #pragma unroll
    for (int mt = 0; mt < 2; mt++)
        #pragma unroll
        for (int nt = 0; nt < 8; nt++)
            #pragma unroll
            for (int r = 0; r < 4; r++) acc[mt][nt][r] = 0.f;

    load_stage(0);
    load_stage(1);
    load_stage(2);

    for (int s = 0; s < S; s++) {
        const int rem = S - 1 - s;
        if (rem >= 2) cp_wait<2>(); else if (rem == 1) cp_wait<1>(); else cp_wait<0>();
        __syncthreads();
        if (s + 3 < S) load_stage(s + 3);

        const uint32_t sb = base + (uint32_t)(s & (NSTAGE - 1)) * STAGE_B;
        #pragma unroll
        for (int ks = 0; ks < 2; ks++) {
            uint32_t ah[2][4];
            #pragma unroll
            for (int mt = 0; mt < 2; mt++)
                ldm4(ah[mt], sb + a_base + (uint32_t)(mt * 16 * 80 + ks * 32));
            uint32_t bh[4][4];
            #pragma unroll
            for (int np = 0; np < 4; np++)
                ldm4(bh[np], sb + ARR_B + b_base + (uint32_t)(np * 16 * 80 + ks * 32));
            #pragma unroll
            for (int mt = 0; mt < 2; mt++)
                #pragma unroll
                for (int nt = 0; nt < 8; nt++) {
                    const int np = nt >> 1, ps = (nt & 1) * 2;
                    mma_bf16(acc[mt][nt], ah[mt], bh[np][ps], bh[np][ps + 1]);
                }
        }
        __syncthreads();
    }

    // Epilogue
    const int g = lane >> 2, t = lane & 3;
    #pragma unroll
    for (int mt = 0; mt < 2; mt++) {
        const int r0 = m0 + wm * 32 + mt * 16 + g;
        #pragma unroll
        for (int nt = 0; nt < 8; nt++) {
            const int col = n0 + wn * 64 + nt * 8 + 2 * t;
            float v0 = acc[mt][nt][0], v1 = acc[mt][nt][1];
            float v2 = acc[mt][nt][2], v3 = acc[mt][nt][3];
            if (MODE != 0) {
                float* d0 = Cf + (long)z * sC + (long)r0 * ldc + coff + col;
                float* d1 = d0 + (long)8 * ldc;
                *reinterpret_cast<float2*>(d0) = make_float2(v0 * scale, v1 * scale);
                *reinterpret_cast<float2*>(d1) = make_float2(v2 * scale, v3 * scale);
            } else {
                const float2 bv = *reinterpret_cast<const float2*>(bias + col);
                __nv_bfloat162 p0, p1;
                p0.x = __float2bfloat16(v0 + bv.x); p0.y = __float2bfloat16(v1 + bv.y);
                p1.x = __float2bfloat16(v2 + bv.x); p1.y = __float2bfloat16(v3 + bv.y);
                __nv_bfloat16* dh0 = Chi + (long)r0 * ldq + col;
                *reinterpret_cast<__nv_bfloat162*>(dh0) = p0;
                *reinterpret_cast<__nv_bfloat162*>(dh0 + 8 * ldq) = p1;
            }
        }
    }
}

// ---------------------------------------------------------------------------
// Per-batch mask prefix scan: qvalid (packed->orig), rank (orig->packed), Lv.
// ---------------------------------------------------------------------------
__global__ void mask_scan(const int* __restrict__ qm,
                          int* __restrict__ qvalid, int* __restrict__ rank,
                          int* __restrict__ Lv)
{
    const int b = blockIdx.x, t = threadIdx.x;
    __shared__ int sc[256];
    const int* m = qm + (long)b * kLQ;
    int mv[4];
    #pragma unroll
    for (int i = 0; i < 4; i++) mv[i] = m[t * 4 + i];
    const int c = mv[0] + mv[1] + mv[2] + mv[3];
    sc[t] = c;
    __syncthreads();
    for (int off = 1; off < 256; off <<= 1) {
        const int v = (t >= off) ? sc[t - off] : 0;
        __syncthreads();
        sc[t] += v;
        __syncthreads();
    }
    int exc = sc[t] - c;
    int* qv = qvalid + (long)b * kLQ;
    int* rk = rank   + (long)b * kLQ;
    #pragma unroll
    for (int i = 0; i < 4; i++) {
        const int q = t * 4 + i;
        if (mv[i]) { rk[q] = exc; qv[exc] = q; exc++; }
        else       { rk[q] = -1; }
    }
    if (t == 255) Lv[b] = sc[255];
}

// ---------------------------------------------------------------------------
// ctx: one read -> output first half copy + bf16 convert
// ---------------------------------------------------------------------------
__global__ void prep_ctx(const float* __restrict__ ctx, float* __restrict__ out,
                         __nv_bfloat16* __restrict__ hi)
{
    const int n4 = kB * kLC * (kD / 4);
    const int i = blockIdx.x * blockDim.x + threadIdx.x;
    if (i >= n4) return;
    const float4 v = reinterpret_cast<const float4*>(ctx)[i];
    const int row = i / (kD / 4);
    const int col = i - row * (kD / 4);
    reinterpret_cast<float4*>(out)[(long)row * (2 * kD / 4) + col] = v;
    __nv_bfloat162 p0; p0.x = __float2bfloat16(v.x); p0.y = __float2bfloat16(v.y);
    __nv_bfloat162 p1; p1.x = __float2bfloat16(v.z); p1.y = __float2bfloat16(v.w);
    reinterpret_cast<__nv_bfloat162*>(hi)[2*i+0] = p0;
    reinterpret_cast<__nv_bfloat162*>(hi)[2*i+1] = p1;
}

// ---------------------------------------------------------------------------
// fp32 -> bf16 convert (qh, W)
// ---------------------------------------------------------------------------
__global__ void split_hi(const float* __restrict__ in,
                         __nv_bfloat16* __restrict__ hi, int n4)
{
    const int i = blockIdx.x * blockDim.x + threadIdx.x;
    if (i >= n4) return;
    const float4 v = reinterpret_cast<const float4*>(in)[i];
    __nv_bfloat162 p0; p0.x = __float2bfloat16(v.x); p0.y = __float2bfloat16(v.y);
    __nv_bfloat162 p1; p1.x = __float2bfloat16(v.z); p1.y = __float2bfloat16(v.w);
    reinterpret_cast<__nv_bfloat162*>(hi)[2*i+0] = p0;
    reinterpret_cast<__nv_bfloat162*>(hi)[2*i+1] = p1;
}

// ---------------------------------------------------------------------------
// qh [B,LQ,D] -> packed transposed qhT [B,D,packed_q] (bf16)
// ---------------------------------------------------------------------------
__global__ void transpose_pack(const float* __restrict__ in,
                               const int* __restrict__ rank,
                               __nv_bfloat16* __restrict__ oh)
{
    __shared__ float t[32][33];
    __shared__ int rk[32];
    const int b  = blockIdx.z;
    const int d0 = blockIdx.x * 32;
    const int q0 = blockIdx.y * 32;
    const int tx = threadIdx.x, ty = threadIdx.y;
    const float* ib = in + (long)b * kLQ * kD;
    #pragma unroll
    for (int j = 0; j < 4; j++)
        t[ty + 8 * j][tx] = ib[(long)(q0 + ty + 8 * j) * kD + d0 + tx];
    if (ty == 0) rk[tx] = rank[(long)b * kLQ + q0 + tx];
    __syncthreads();
    const int col = rk[tx];
    if (col < 0) return;
    __nv_bfloat16* bh = oh + (long)b * kD * kLQ;
    #pragma unroll
    for (int j = 0; j < 4; j++) {
        const float v = t[tx][ty + 8 * j];
        bh[(long)(d0 + ty + 8 * j) * kLQ + col] = __float2bfloat16(v);
    }
}

// ---------------------------------------------------------------------------
// Softmax over packed columns [0, Lv); writes p_hi with zeros for j >= Lv.
// ---------------------------------------------------------------------------
__global__ void softmax_packed(const float* __restrict__ scores,
                               const int* __restrict__ LvArr,
                               __nv_bfloat16* __restrict__ phi)
{
    const int row = blockIdx.x;              // 0 .. B*LC-1
    const int b   = row >> 11;               // / kLC
    const int lv  = __ldg(&LvArr[b]);
    const float* s = scores + (long)row * kLQ;

    const int t = threadIdx.x;               // 256 threads, 4 elems each
    float v[4]; int ok[4];
    float mx = -1e30f;
    #pragma unroll
    for (int i = 0; i < 4; i++) {
        const int q = t + i * 256;
        ok[i] = (q < lv);
        v[i]  = ok[i] ? s[q] : 0.f;
        if (ok[i]) mx = fmaxf(mx, v[i]);
    }

    __shared__ float smax[8];
    __shared__ float ssum[8];

    #pragma unroll
    for (int off = 16; off; off >>= 1)
        mx = fmaxf(mx, __shfl_xor_sync(0xffffffffu, mx, off));
    if ((t & 31) == 0) smax[t >> 5] = mx;
    __syncthreads();
    float bm = -1e30f;
    #pragma unroll
    for (int w = 0; w < 8; w++) bm = fmaxf(bm, smax[w]);

    float e[4];
    float sum = 0.f;
    #pragma unroll
    for (int i = 0; i < 4; i++) {
        e[i] = ok[i] ? __expf(v[i] - bm) : 0.f;
        sum += e[i];
    }
    #pragma unroll
    for (int off = 16; off; off >>= 1)
        sum += __shfl_xor_sync(0xffffffffu, sum, off);
    if ((t & 31) == 0) ssum[t >> 5] = sum;
    __syncthreads();
    float total = 0.f;
    #pragma unroll
    for (int w = 0; w < 8; w++) total += ssum[w];

    const float inv = 1.f / total;
    __nv_bfloat16* dh = phi + (long)row * kLQ;
    #pragma unroll
    for (int i = 0; i < 4; i++) {
        const int q = t + i * 256;
        dh[q] = __float2bfloat16(e[i] * inv);   // 0 for q >= lv
    }
}

// ---------------------------------------------------------------------------
extern "C" void kernel_launch(void* const* d_in, const int* in_sizes, int n_in,
                              void* d_out, int out_size)
{
    const float* ctx  = (const float*)d_in[0];
    const float* qh   = (const float*)d_in[2];
    const int*   qm   = (const int*)d_in[3];
    const float* W    = (const float*)d_in[4];
    const float* bias = (const float*)d_in[5];
    float* out = (float*)d_out;
    (void)in_sizes; (void)n_in; (void)out_size;

    __nv_bfloat16 *ctx_hi, *qh_hi, *qhT_hi, *W_hi, *q_hi, *p_hi;
    float* scores;
    int *qvalid, *rank, *Lv;
    cudaGetSymbolAddress((void**)&ctx_hi, g_ctx_hi);
    cudaGetSymbolAddress((void**)&qh_hi,  g_qh_hi);
    cudaGetSymbolAddress((void**)&qhT_hi, g_qhT_hi);
    cudaGetSymbolAddress((void**)&W_hi,   g_W_hi);
    cudaGetSymbolAddress((void**)&q_hi,   g_q_hi);
    cudaGetSymbolAddress((void**)&p_hi,   g_p_hi);
    cudaGetSymbolAddress((void**)&scores, g_scores);
    cudaGetSymbolAddress((void**)&qvalid, g_qvalid);
    cudaGetSymbolAddress((void**)&rank,   g_rank);
    cudaGetSymbolAddress((void**)&Lv,     g_Lv);

    cudaFuncSetAttribute(gemm_tc<0>, cudaFuncAttributeMaxDynamicSharedMemorySize, SMEM_SZ);
    cudaFuncSetAttribute(gemm_tc<1>, cudaFuncAttributeMaxDynamicSharedMemorySize, SMEM_SZ);
    cudaFuncSetAttribute(gemm_tc<2>, cudaFuncAttributeMaxDynamicSharedMemorySize, SMEM_SZ);

    // --- prep ---
    prep_ctx<<<(kB * kLC * (kD / 4) + 255) / 256, 256>>>(ctx, out, ctx_hi);
    split_hi<<<(kB * kLQ * kD / 4 + 255) / 256, 256>>>(qh, qh_hi, kB * kLQ * kD / 4);
    split_hi<<<(kD * kD / 4 + 255) / 256, 256>>>(W, W_hi, kD * kD / 4);
    mask_scan<<<kB, 256>>>(qm, qvalid, rank, Lv);
    transpose_pack<<<dim3(kD / 32, kLQ / 32, kB), dim3(32, 8)>>>(qh, rank, qhT_hi);

    // --- K1: query = qh_hi @ W_hi^T + b -> bf16 ---
    gemm_tc<0><<<dim3(kD / 128, (kB * kLQ) / 128, 1), 256, SMEM_SZ>>>(
        qh_hi, 0, kD,
        W_hi, 0, kD, kD,
        nullptr, 0, 0, 0, 1.0f, bias,
        q_hi, kD, nullptr, nullptr);

    // --- K2: packed scores = scale * ctx_hi @ q_hi[qvalid]^T ---
    gemm_tc<1><<<dim3(kLQ / 128, kLC / 128, kB), 256, SMEM_SZ>>>(
        ctx_hi, (long)kLC * kD, kD,
        q_hi, (long)kLQ * kD, kD, kD,
        scores, (long)kLC * kLQ, kLQ, 0, kScale, nullptr,
        nullptr, 0, qvalid, Lv);

    // --- K3: softmax over packed columns -> p_hi (zeros beyond Lv) ---
    softmax_packed<<<kB * kLC, 256>>>(scores, Lv, p_hi);

    // --- K4: out[:, D:] = p_hi @ qhT_hi^T (runtime K = pad128(Lv)) ---
    gemm_tc<2><<<dim3(kD / 128, kLC / 128, kB), 256, SMEM_SZ>>>(
        p_hi, (long)kLC * kLQ, kLQ,
        qhT_hi, (long)kD * kLQ, kLQ, 0,
        out, (long)kLC * 2 * kD, 2 * kD, kD, 1.0f, nullptr,
        nullptr, 0, nullptr, Lv);
}

// round 9
// speedup vs baseline: 8.8336x; 1.0762x over previous
#include <cuda_runtime.h>
#include <cuda_bf16.h>
#include <cstdint>

// Problem constants (fixed shapes from setup_inputs)
static constexpr int kB  = 8;
static constexpr int kLC = 2048;
static constexpr int kLQ = 1024;
static constexpr int kD  = 768;
static constexpr float kScale = 0.036084391824351615f; // 1/sqrt(768)

// ---------------------------------------------------------------------------
// Scratch (__device__ globals; no allocs allowed) — pure bf16 pipeline
// ---------------------------------------------------------------------------
__device__ __nv_bfloat16 g_ctx_hi [(size_t)kB * kLC * kD];
__device__ __nv_bfloat16 g_qh_pk  [(size_t)kB * kLQ * kD];   // PACKED valid qh rows
__device__ __nv_bfloat16 g_qhT_hi [(size_t)kB * kD * kLQ];   // PACKED transposed
__device__ __nv_bfloat16 g_W_hi   [(size_t)kD * kD];
__device__ __nv_bfloat16 g_q_hi   [(size_t)kB * kLQ * kD];   // projected query (packed rows)
__device__ float         g_scores [(size_t)kB * kLC * kLQ];  // packed cols
__device__ __nv_bfloat16 g_p_hi   [(size_t)kB * kLC * kLQ];  // packed probs
__device__ int           g_qvalid [kB * kLQ];                // packed->orig q
__device__ int           g_Lv     [kB];                      // valid count per batch

// ---------------------------------------------------------------------------
// PTX helpers — base sm_103 instructions only (NO tcgen05 in this toolchain)
// ---------------------------------------------------------------------------
__device__ __forceinline__ uint32_t smem_u32(const void* p) {
    uint32_t a;
    asm("{ .reg .u64 t; cvta.to.shared.u64 t, %1; cvt.u32.u64 %0, t; }" : "=r"(a) : "l"(p));
    return a;
}
__device__ __forceinline__ void cp16(uint32_t dst, const void* src) {
    asm volatile("cp.async.cg.shared.global [%0], [%1], 16;" :: "r"(dst), "l"(src) : "memory");
}
__device__ __forceinline__ void cp_commit() { asm volatile("cp.async.commit_group;" ::: "memory"); }
template<int N> __device__ __forceinline__ void cp_wait() {
    asm volatile("cp.async.wait_group %0;" :: "n"(N) : "memory");
}
__device__ __forceinline__ void ldm4(uint32_t* r, uint32_t addr) {
    asm volatile("ldmatrix.sync.aligned.m8n8.x4.shared.b16 {%0,%1,%2,%3}, [%4];"
                 : "=r"(r[0]), "=r"(r[1]), "=r"(r[2]), "=r"(r[3]) : "r"(addr));
}
__device__ __forceinline__ void mma_bf16(float* c, const uint32_t* a, uint32_t b0, uint32_t b1) {
    asm volatile("mma.sync.aligned.m16n8k16.row.col.f32.bf16.bf16.f32 "
                 "{%0,%1,%2,%3}, {%4,%5,%6,%7}, {%8,%9}, {%0,%1,%2,%3};"
                 : "+f"(c[0]), "+f"(c[1]), "+f"(c[2]), "+f"(c[3])
                 : "r"(a[0]), "r"(a[1]), "r"(a[2]), "r"(a[3]), "r"(b0), "r"(b1));
}

// ---------------------------------------------------------------------------
// Tensor-core NT GEMM, single-term bf16, fp32 accumulate: acc = A*B^T
// CTA tile 128x128, BK=32, 4-stage cp.async pipeline (2 arrays/stage = 80KB),
// 8 warps (4Mx2N), warp tile 32x64, 2 CTAs/SM.
// MODE 0 (K1): batched A; M-early-exit at pad128(Lv[z]); +bias; out -> bf16
// MODE 1 (K2): N-early-exit at Lv[z]; out=acc*scale fp32
// MODE 2 (K4): runtime K=pad128(Lv[z]); out=acc fp32 at [.., coff+col]
// ---------------------------------------------------------------------------
static constexpr int ARR_B   = 10240;      // 128 rows * 80B (64B data + 16B pad)
static constexpr int STAGE_B = 2 * ARR_B;  // A, B
static constexpr int NSTAGE  = 4;
static constexpr int SMEM_SZ = NSTAGE * STAGE_B;  // 81920

template<int MODE>
__global__ void __launch_bounds__(256, 2)
gemm_tc(const __nv_bfloat16* __restrict__ Ahi, long sA, int lda,
        const __nv_bfloat16* __restrict__ Bhi, long sB, int ldb, int Kstatic,
        float* __restrict__ Cf, long sC, int ldc, int coff, float scale,
        const float* __restrict__ bias,
        __nv_bfloat16* __restrict__ Chi, long sQ, int ldq,
        const int* __restrict__ LvArr)
{
    const int z  = blockIdx.z;
    const int m0 = blockIdx.y * 128;
    const int n0 = blockIdx.x * 128;

    const int lv = __ldg(&LvArr[z]);
    if (MODE == 0 && m0 >= ((lv + 127) & ~127)) return;   // only packed query rows
    if (MODE == 1 && n0 >= lv) return;                    // only valid q columns

    int Ktot = Kstatic;
    if (MODE == 2) Ktot = (lv + 127) & ~127;

    extern __shared__ __align__(128) char dsm[];
    const uint32_t base = smem_u32(dsm);

    const int tid  = threadIdx.x;
    const int wid  = tid >> 5;
    const int lane = tid & 31;
    const int wm   = wid & 3;
    const int wn   = wid >> 2;

    const __nv_bfloat16* pAh = Ahi + (long)z * sA + (long)m0 * lda;
    const __nv_bfloat16* pBh = Bhi + (long)z * sB + (long)n0 * ldb;

    const int S = Ktot >> 5;           // BK=32 stages (>=4 always)

    auto load_stage = [&](int s) {
        const uint32_t sb = base + (uint32_t)(s & (NSTAGE - 1)) * STAGE_B;
        const int k0 = s << 5;
        const int r  = tid >> 2;
        const int ch = tid & 3;
        cp16(sb + r * 80 + ch * 16,        pAh + (long)r * lda + k0 + ch * 8);
        cp16(sb + (r + 64) * 80 + ch * 16, pAh + (long)(r + 64) * lda + k0 + ch * 8);
        cp16(sb + ARR_B + r * 80 + ch * 16,        pBh + (long)r * ldb + k0 + ch * 8);
        cp16(sb + ARR_B + (r + 64) * 80 + ch * 16, pBh + (long)(r + 64) * ldb + k0 + ch * 8);
        cp_commit();
    };

    // ldmatrix per-lane address components
    const int ati = lane >> 3;
    const int a_row = (lane & 7) + (ati & 1) * 8;
    const int a_col = (ati >> 1) * 16;
    const uint32_t a_base = (uint32_t)((wm * 32 + a_row) * 80 + a_col);
    const int b_row = (ati >> 1) * 8 + (lane & 7);
    const int b_col = (ati & 1) * 16;
    const uint32_t b_base = (uint32_t)((wn * 64 + b_row) * 80 + b_col);

    float acc[2][8][4];
    #pragma unroll
    for (int mt = 0; mt < 2; mt++)
        #pragma unroll
        for (int nt = 0; nt < 8; nt++)
            #pragma unroll
            for (int r = 0; r < 4; r++) acc[mt][nt][r] = 0.f;

    load_stage(0);
    load_stage(1);
    load_stage(2);

    for (int s = 0; s < S; s++) {
        const int rem = S - 1 - s;
        if (rem >= 2) cp_wait<2>(); else if (rem == 1) cp_wait<1>(); else cp_wait<0>();
        __syncthreads();
        if (s + 3 < S) load_stage(s + 3);

        const uint32_t sb = base + (uint32_t)(s & (NSTAGE - 1)) * STAGE_B;
        #pragma unroll
        for (int ks = 0; ks < 2; ks++) {
            uint32_t ah[2][4];
            #pragma unroll
            for (int mt = 0; mt < 2; mt++)
                ldm4(ah[mt], sb + a_base + (uint32_t)(mt * 16 * 80 + ks * 32));
            uint32_t bh[4][4];
            #pragma unroll
            for (int np = 0; np < 4; np++)
                ldm4(bh[np], sb + ARR_B + b_base + (uint32_t)(np * 16 * 80 + ks * 32));
            #pragma unroll
            for (int mt = 0; mt < 2; mt++)
                #pragma unroll
                for (int nt = 0; nt < 8; nt++) {
                    const int np = nt >> 1, ps = (nt & 1) * 2;
                    mma_bf16(acc[mt][nt], ah[mt], bh[np][ps], bh[np][ps + 1]);
                }
        }
        __syncthreads();
    }

    // Epilogue
    const int g = lane >> 2, t = lane & 3;
    #pragma unroll
    for (int mt = 0; mt < 2; mt++) {
        const int r0 = m0 + wm * 32 + mt * 16 + g;
        #pragma unroll
        for (int nt = 0; nt < 8; nt++) {
            const int col = n0 + wn * 64 + nt * 8 + 2 * t;
            float v0 = acc[mt][nt][0], v1 = acc[mt][nt][1];
            float v2 = acc[mt][nt][2], v3 = acc[mt][nt][3];
            if (MODE != 0) {
                float* d0 = Cf + (long)z * sC + (long)r0 * ldc + coff + col;
                float* d1 = d0 + (long)8 * ldc;
                *reinterpret_cast<float2*>(d0) = make_float2(v0 * scale, v1 * scale);
                *reinterpret_cast<float2*>(d1) = make_float2(v2 * scale, v3 * scale);
            } else {
                const float2 bv = *reinterpret_cast<const float2*>(bias + col);
                __nv_bfloat162 p0, p1;
                p0.x = __float2bfloat16(v0 + bv.x); p0.y = __float2bfloat16(v1 + bv.y);
                p1.x = __float2bfloat16(v2 + bv.x); p1.y = __float2bfloat16(v3 + bv.y);
                __nv_bfloat16* dh0 = Chi + (long)z * sQ + (long)r0 * ldq + col;
                *reinterpret_cast<__nv_bfloat162*>(dh0) = p0;
                *reinterpret_cast<__nv_bfloat162*>(dh0 + 8 * ldq) = p1;
            }
        }
    }
}

// ---------------------------------------------------------------------------
// Per-batch mask prefix scan: qvalid (packed->orig) and Lv.
// ---------------------------------------------------------------------------
__global__ void mask_scan(const int* __restrict__ qm,
                          int* __restrict__ qvalid, int* __restrict__ Lv)
{
    const int b = blockIdx.x, t = threadIdx.x;
    __shared__ int sc[256];
    const int* m = qm + (long)b * kLQ;
    int mv[4];
    #pragma unroll
    for (int i = 0; i < 4; i++) mv[i] = m[t * 4 + i];
    const int c = mv[0] + mv[1] + mv[2] + mv[3];
    sc[t] = c;
    __syncthreads();
    for (int off = 1; off < 256; off <<= 1) {
        const int v = (t >= off) ? sc[t - off] : 0;
        __syncthreads();
        sc[t] += v;
        __syncthreads();
    }
    int exc = sc[t] - c;
    int* qv = qvalid + (long)b * kLQ;
    #pragma unroll
    for (int i = 0; i < 4; i++) {
        const int q = t * 4 + i;
        if (mv[i]) { qv[exc] = q; exc++; }
    }
    if (t == 255) Lv[b] = sc[255];
}

// ---------------------------------------------------------------------------
// qh -> (a) packed bf16 rows [B, packed_q, D]   (K1's A operand)
//       (b) packed transposed [B, D, packed_q]  (K4's B operand)
// One qh read. Packed rows j >= Lv are zero-filled. Tiles with
// q0 >= pad128(Lv) skipped (nothing reads them).
// ---------------------------------------------------------------------------
__global__ void gather_pack(const float* __restrict__ in,
                            const int* __restrict__ qvalid,
                            const int* __restrict__ LvArr,
                            __nv_bfloat16* __restrict__ pk,
                            __nv_bfloat16* __restrict__ oT)
{
    const int b  = blockIdx.z;
    const int lv = __ldg(&LvArr[b]);
    const int q0 = blockIdx.y * 32;               // packed row tile
    if (q0 >= ((lv + 127) & ~127)) return;
    const int d0 = blockIdx.x * 32;
    const int tx = threadIdx.x, ty = threadIdx.y;

    __shared__ float t[32][33];
    __shared__ int src[32];
    if (ty == 0) {
        const int j = q0 + tx;
        src[tx] = (j < lv) ? __ldg(&qvalid[b * kLQ + j]) : -1;
    }
    __syncthreads();

    const float* ib = in + (long)b * kLQ * kD;
    __nv_bfloat16* pb = pk + (long)b * kLQ * kD;
    #pragma unroll
    for (int j = 0; j < 4; j++) {
        const int row = ty + 8 * j;               // packed row within tile
        const int sq  = src[row];
        const float v = (sq >= 0) ? ib[(long)sq * kD + d0 + tx] : 0.f;
        t[row][tx] = v;
        pb[(long)(q0 + row) * kD + d0 + tx] = __float2bfloat16(v);
    }
    __syncthreads();
    __nv_bfloat16* bh = oT + (long)b * kD * kLQ;
    #pragma unroll
    for (int j = 0; j < 4; j++) {
        const float v = t[tx][ty + 8 * j];
        bh[(long)(d0 + ty + 8 * j) * kLQ + q0 + tx] = __float2bfloat16(v);
    }
}

// ---------------------------------------------------------------------------
// ctx: one read -> output first half copy + bf16 convert
// ---------------------------------------------------------------------------
__global__ void prep_ctx(const float* __restrict__ ctx, float* __restrict__ out,
                         __nv_bfloat16* __restrict__ hi)
{
    const int n4 = kB * kLC * (kD / 4);
    const int i = blockIdx.x * blockDim.x + threadIdx.x;
    if (i >= n4) return;
    const float4 v = reinterpret_cast<const float4*>(ctx)[i];
    const int row = i / (kD / 4);
    const int col = i - row * (kD / 4);
    reinterpret_cast<float4*>(out)[(long)row * (2 * kD / 4) + col] = v;
    __nv_bfloat162 p0; p0.x = __float2bfloat16(v.x); p0.y = __float2bfloat16(v.y);
    __nv_bfloat162 p1; p1.x = __float2bfloat16(v.z); p1.y = __float2bfloat16(v.w);
    reinterpret_cast<__nv_bfloat162*>(hi)[2*i+0] = p0;
    reinterpret_cast<__nv_bfloat162*>(hi)[2*i+1] = p1;
}

// ---------------------------------------------------------------------------
// fp32 -> bf16 convert (W)
// ---------------------------------------------------------------------------
__global__ void split_hi(const float* __restrict__ in,
                         __nv_bfloat16* __restrict__ hi, int n4)
{
    const int i = blockIdx.x * blockDim.x + threadIdx.x;
    if (i >= n4) return;
    const float4 v = reinterpret_cast<const float4*>(in)[i];
    __nv_bfloat162 p0; p0.x = __float2bfloat16(v.x); p0.y = __float2bfloat16(v.y);
    __nv_bfloat162 p1; p1.x = __float2bfloat16(v.z); p1.y = __float2bfloat16(v.w);
    reinterpret_cast<__nv_bfloat162*>(hi)[2*i+0] = p0;
    reinterpret_cast<__nv_bfloat162*>(hi)[2*i+1] = p1;
}

// ---------------------------------------------------------------------------
// Softmax over packed columns [0, Lv); writes p_hi zeros in [Lv, pad128(Lv)).
// ---------------------------------------------------------------------------
__global__ void softmax_packed(const float* __restrict__ scores,
                               const int* __restrict__ LvArr,
                               __nv_bfloat16* __restrict__ phi)
{
    const int row = blockIdx.x;              // 0 .. B*LC-1
    const int b   = row >> 11;               // / kLC
    const int lv  = __ldg(&LvArr[b]);
    const int lim = (lv + 127) & ~127;
    const float* s = scores + (long)row * kLQ;

    const int t = threadIdx.x;               // 256 threads, 4 elems each
    float v[4]; int ok[4];
    float mx = -1e30f;
    #pragma unroll
    for (int i = 0; i < 4; i++) {
        const int q = t + i * 256;
        ok[i] = (q < lv);
        v[i]  = ok[i] ? s[q] : 0.f;
        if (ok[i]) mx = fmaxf(mx, v[i]);
    }

    __shared__ float smax[8];
    __shared__ float ssum[8];

    #pragma unroll
    for (int off = 16; off; off >>= 1)
        mx = fmaxf(mx, __shfl_xor_sync(0xffffffffu, mx, off));
    if ((t & 31) == 0) smax[t >> 5] = mx;
    __syncthreads();
    float bm = -1e30f;
    #pragma unroll
    for (int w = 0; w < 8; w++) bm = fmaxf(bm, smax[w]);

    float e[4];
    float sum = 0.f;
    #pragma unroll
    for (int i = 0; i < 4; i++) {
        e[i] = ok[i] ? __expf(v[i] - bm) : 0.f;
        sum += e[i];
    }
    #pragma unroll
    for (int off = 16; off; off >>= 1)
        sum += __shfl_xor_sync(0xffffffffu, sum, off);
    if ((t & 31) == 0) ssum[t >> 5] = sum;
    __syncthreads();
    float total = 0.f;
    #pragma unroll
    for (int w = 0; w < 8; w++) total += ssum[w];

    const float inv = 1.f / total;
    __nv_bfloat16* dh = phi + (long)row * kLQ;
    #pragma unroll
    for (int i = 0; i < 4; i++) {
        const int q = t + i * 256;
        if (q < lim) dh[q] = __float2bfloat16(e[i] * inv);   // 0 for q in [lv, lim)
    }
}

// ---------------------------------------------------------------------------
extern "C" void kernel_launch(void* const* d_in, const int* in_sizes, int n_in,
                              void* d_out, int out_size)
{
    const float* ctx  = (const float*)d_in[0];
    const float* qh   = (const float*)d_in[2];
    const int*   qm   = (const int*)d_in[3];
    const float* W    = (const float*)d_in[4];
    const float* bias = (const float*)d_in[5];
    float* out = (float*)d_out;
    (void)in_sizes; (void)n_in; (void)out_size;

    __nv_bfloat16 *ctx_hi, *qh_pk, *qhT_hi, *W_hi, *q_hi, *p_hi;
    float* scores;
    int *qvalid, *Lv;
    cudaGetSymbolAddress((void**)&ctx_hi, g_ctx_hi);
    cudaGetSymbolAddress((void**)&qh_pk,  g_qh_pk);
    cudaGetSymbolAddress((void**)&qhT_hi, g_qhT_hi);
    cudaGetSymbolAddress((void**)&W_hi,   g_W_hi);
    cudaGetSymbolAddress((void**)&q_hi,   g_q_hi);
    cudaGetSymbolAddress((void**)&p_hi,   g_p_hi);
    cudaGetSymbolAddress((void**)&scores, g_scores);
    cudaGetSymbolAddress((void**)&qvalid, g_qvalid);
    cudaGetSymbolAddress((void**)&Lv,     g_Lv);

    cudaFuncSetAttribute(gemm_tc<0>, cudaFuncAttributeMaxDynamicSharedMemorySize, SMEM_SZ);
    cudaFuncSetAttribute(gemm_tc<1>, cudaFuncAttributeMaxDynamicSharedMemorySize, SMEM_SZ);
    cudaFuncSetAttribute(gemm_tc<2>, cudaFuncAttributeMaxDynamicSharedMemorySize, SMEM_SZ);

    // Launch order puts K1 at slot #4 (ncu captures the 4th launch).
    // (1) W convert
    split_hi<<<(kD * kD / 4 + 255) / 256, 256>>>(W, W_hi, kD * kD / 4);
    // (2) mask scan
    mask_scan<<<kB, 256>>>(qm, qvalid, Lv);
    // (3) qh single-pass: packed rows + packed transpose
    gather_pack<<<dim3(kD / 32, kLQ / 32, kB), dim3(32, 8)>>>(qh, qvalid, Lv, qh_pk, qhT_hi);
    // (4) K1: query[packed] = qh_pk @ W^T + b -> bf16 (M-early-exit per batch)
    gemm_tc<0><<<dim3(kD / 128, kLQ / 128, kB), 256, SMEM_SZ>>>(
        qh_pk, (long)kLQ * kD, kD,
        W_hi, 0, kD, kD,
        nullptr, 0, 0, 0, 1.0f, bias,
        q_hi, (long)kLQ * kD, kD, Lv);
    // (5) ctx copy + convert
    prep_ctx<<<(kB * kLC * (kD / 4) + 255) / 256, 256>>>(ctx, out, ctx_hi);
    // (6) K2: packed scores = scale * ctx_hi @ q_hi^T (N-early-exit at Lv)
    gemm_tc<1><<<dim3(kLQ / 128, kLC / 128, kB), 256, SMEM_SZ>>>(
        ctx_hi, (long)kLC * kD, kD,
        q_hi, (long)kLQ * kD, kD, kD,
        scores, (long)kLC * kLQ, kLQ, 0, kScale, nullptr,
        nullptr, 0, 0, Lv);
    // (7) softmax -> p_hi (zeros in pad region)
    softmax_packed<<<kB * kLC, 256>>>(scores, Lv, p_hi);
    // (8) K4: out[:, D:] = p_hi @ qhT_hi^T (runtime K = pad128(Lv))
    gemm_tc<2><<<dim3(kD / 128, kLC / 128, kB), 256, SMEM_SZ>>>(
        p_hi, (long)kLC * kLQ, kLQ,
        qhT_hi, (long)kD * kLQ, kLQ, 0,
        out, (long)kLC * 2 * kD, 2 * kD, kD, 1.0f, nullptr,
        nullptr, 0, 0, Lv);
}

// round 11
// speedup vs baseline: 8.9818x; 1.0168x over previous
#include <cuda_runtime.h>
#include <cuda_bf16.h>
#include <cstdint>

// Problem constants (fixed shapes from setup_inputs)
static constexpr int kB  = 8;
static constexpr int kLC = 2048;
static constexpr int kLQ = 1024;
static constexpr int kD  = 768;
static constexpr float kScale = 0.036084391824351615f; // 1/sqrt(768)

// ---------------------------------------------------------------------------
// Scratch (__device__ globals; no allocs allowed) — pure bf16 pipeline
// ---------------------------------------------------------------------------
__device__ __nv_bfloat16 g_ctx_hi [(size_t)kB * kLC * kD];
__device__ __nv_bfloat16 g_qh_pk  [(size_t)kB * kLQ * kD];   // PACKED valid qh rows
__device__ __nv_bfloat16 g_qhT_hi [(size_t)kB * kD * kLQ];   // PACKED transposed
__device__ __nv_bfloat16 g_W_hi   [(size_t)kD * kD];
__device__ __nv_bfloat16 g_q_hi   [(size_t)kB * kLQ * kD];   // projected query (packed rows)
__device__ float         g_scores [(size_t)kB * kLC * kLQ];  // packed cols
__device__ __nv_bfloat16 g_p_hi   [(size_t)kB * kLC * kLQ];  // packed probs
__device__ int           g_qvalid [kB * kLQ];                // packed->orig q
__device__ int           g_Lv     [kB];                      // valid count per batch

// ---------------------------------------------------------------------------
// PTX helpers — base sm_103 instructions only (NO tcgen05 in this toolchain)
// ---------------------------------------------------------------------------
__device__ __forceinline__ uint32_t smem_u32(const void* p) {
    uint32_t a;
    asm("{ .reg .u64 t; cvta.to.shared.u64 t, %1; cvt.u32.u64 %0, t; }" : "=r"(a) : "l"(p));
    return a;
}
__device__ __forceinline__ void cp16(uint32_t dst, const void* src) {
    asm volatile("cp.async.cg.shared.global [%0], [%1], 16;" :: "r"(dst), "l"(src) : "memory");
}
__device__ __forceinline__ void cp_commit() { asm volatile("cp.async.commit_group;" ::: "memory"); }
template<int N> __device__ __forceinline__ void cp_wait() {
    asm volatile("cp.async.wait_group %0;" :: "n"(N) : "memory");
}
__device__ __forceinline__ void ldm4(uint32_t* r, uint32_t addr) {
    asm volatile("ldmatrix.sync.aligned.m8n8.x4.shared.b16 {%0,%1,%2,%3}, [%4];"
                 : "=r"(r[0]), "=r"(r[1]), "=r"(r[2]), "=r"(r[3]) : "r"(addr));
}
__device__ __forceinline__ void mma_bf16(float* c, const uint32_t* a, uint32_t b0, uint32_t b1) {
    asm volatile("mma.sync.aligned.m16n8k16.row.col.f32.bf16.bf16.f32 "
                 "{%0,%1,%2,%3}, {%4,%5,%6,%7}, {%8,%9}, {%0,%1,%2,%3};"
                 : "+f"(c[0]), "+f"(c[1]), "+f"(c[2]), "+f"(c[3])
                 : "r"(a[0]), "r"(a[1]), "r"(a[2]), "r"(a[3]), "r"(b0), "r"(b1));
}

// ---------------------------------------------------------------------------
// Tensor-core NT GEMM, single-term bf16, fp32 accumulate: acc = A*B^T
// CTA tile 128x128, BK=32, 4-stage cp.async pipeline (2 arrays/stage = 80KB),
// 8 warps (4Mx2N), warp tile 32x64, 2 CTAs/SM. ONE barrier per stage
// (the leading sync after cp_wait also orders smem buffer reuse — the buffer
// written by load_stage(s+3) was last read at iter s-1, and all warps passed
// this iteration's leading sync only after finishing iter s-1's compute).
// MODE 0 (K1): batched A; M-early-exit at pad128(Lv[z]); +bias; out -> bf16
// MODE 1 (K2): N-early-exit at Lv[z]; out=acc*scale fp32
// MODE 2 (K4): runtime K=pad128(Lv[z]); out=acc fp32 at [.., coff+col]
// ---------------------------------------------------------------------------
static constexpr int ARR_B   = 10240;      // 128 rows * 80B (64B data + 16B pad)
static constexpr int STAGE_B = 2 * ARR_B;  // A, B
static constexpr int NSTAGE  = 4;
static constexpr int SMEM_SZ = NSTAGE * STAGE_B;  // 81920

template<int MODE>
__global__ void __launch_bounds__(256, 2)
gemm_tc(const __nv_bfloat16* __restrict__ Ahi, long sA, int lda,
        const __nv_bfloat16* __restrict__ Bhi, long sB, int ldb, int Kstatic,
        float* __restrict__ Cf, long sC, int ldc, int coff, float scale,
        const float* __restrict__ bias,
        __nv_bfloat16* __restrict__ Chi, long sQ, int ldq,
        const int* __restrict__ LvArr)
{
    const int z  = blockIdx.z;
    const int m0 = blockIdx.y * 128;
    const int n0 = blockIdx.x * 128;

    const int lv = __ldg(&LvArr[z]);
    if (MODE == 0 && m0 >= ((lv + 127) & ~127)) return;   // only packed query rows
    if (MODE == 1 && n0 >= lv) return;                    // only valid q columns

    int Ktot = Kstatic;
    if (MODE == 2) Ktot = (lv + 127) & ~127;

    extern __shared__ __align__(128) char dsm[];
    const uint32_t base = smem_u32(dsm);

    const int tid  = threadIdx.x;
    const int wid  = tid >> 5;
    const int lane = tid & 31;
    const int wm   = wid & 3;
    const int wn   = wid >> 2;

    const __nv_bfloat16* pAh = Ahi + (long)z * sA + (long)m0 * lda;
    const __nv_bfloat16* pBh = Bhi + (long)z * sB + (long)n0 * ldb;

    const int S = Ktot >> 5;           // BK=32 stages (>=4 always)

    auto load_stage = [&](int s) {
        const uint32_t sb = base + (uint32_t)(s & (NSTAGE - 1)) * STAGE_B;
        const int k0 = s << 5;
        const int r  = tid >> 2;
        const int ch = tid & 3;
        cp16(sb + r * 80 + ch * 16,        pAh + (long)r * lda + k0 + ch * 8);
        cp16(sb + (r + 64) * 80 + ch * 16, pAh + (long)(r + 64) * lda + k0 + ch * 8);
        cp16(sb + ARR_B + r * 80 + ch * 16,        pBh + (long)r * ldb + k0 + ch * 8);
        cp16(sb + ARR_B + (r + 64) * 80 + ch * 16, pBh + (long)(r + 64) * ldb + k0 + ch * 8);
        cp_commit();
    };

    // ldmatrix per-lane address components
    const int ati = lane >> 3;
    const int a_row = (lane & 7) + (ati & 1) * 8;
    const int a_col = (ati >> 1) * 16;
    const uint32_t a_base = (uint32_t)((wm * 32 + a_row) * 80 + a_col);
    const int b_row = (ati >> 1) * 8 + (lane & 7);
    const int b_col = (ati & 1) * 16;
    const uint32_t b_base = (uint32_t)((wn * 64 + b_row) * 80 + b_col);

    float acc[2][8][4];
    #pragma unroll
    for (int mt = 0; mt < 2; mt++)
        #pragma unroll
        for (int nt = 0; nt < 8; nt++)
            #pragma unroll
            for (int r = 0; r < 4; r++) acc[mt][nt][r] = 0.f;

    load_stage(0);
    load_stage(1);
    load_stage(2);

    for (int s = 0; s < S; s++) {
        const int rem = S - 1 - s;
        if (rem >= 2) cp_wait<2>(); else if (rem == 1) cp_wait<1>(); else cp_wait<0>();
        __syncthreads();                    // single barrier per stage
        if (s + 3 < S) load_stage(s + 3);

        const uint32_t sb = base + (uint32_t)(s & (NSTAGE - 1)) * STAGE_B;
        #pragma unroll
        for (int ks = 0; ks < 2; ks++) {
            uint32_t ah[2][4];
            #pragma unroll
            for (int mt = 0; mt < 2; mt++)
                ldm4(ah[mt], sb + a_base + (uint32_t)(mt * 16 * 80 + ks * 32));
            uint32_t bh[4][4];
            #pragma unroll
            for (int np = 0; np < 4; np++)
                ldm4(bh[np], sb + ARR_B + b_base + (uint32_t)(np * 16 * 80 + ks * 32));
            #pragma unroll
            for (int mt = 0; mt < 2; mt++)
                #pragma unroll
                for (int nt = 0; nt < 8; nt++) {
                    const int np = nt >> 1, ps = (nt & 1) * 2;
                    mma_bf16(acc[mt][nt], ah[mt], bh[np][ps], bh[np][ps + 1]);
                }
        }
    }

    // Epilogue
    const int g = lane >> 2, t = lane & 3;
    #pragma unroll
    for (int mt = 0; mt < 2; mt++) {
        const int r0 = m0 + wm * 32 + mt * 16 + g;
        #pragma unroll
        for (int nt = 0; nt < 8; nt++) {
            const int col = n0 + wn * 64 + nt * 8 + 2 * t;
            float v0 = acc[mt][nt][0], v1 = acc[mt][nt][1];
            float v2 = acc[mt][nt][2], v3 = acc[mt][nt][3];
            if (MODE != 0) {
                float* d0 = Cf + (long)z * sC + (long)r0 * ldc + coff + col;
                float* d1 = d0 + (long)8 * ldc;
                *reinterpret_cast<float2*>(d0) = make_float2(v0 * scale, v1 * scale);
                *reinterpret_cast<float2*>(d1) = make_float2(v2 * scale, v3 * scale);
            } else {
                const float2 bv = *reinterpret_cast<const float2*>(bias + col);
                __nv_bfloat162 p0, p1;
                p0.x = __float2bfloat16(v0 + bv.x); p0.y = __float2bfloat16(v1 + bv.y);
                p1.x = __float2bfloat16(v2 + bv.x); p1.y = __float2bfloat16(v3 + bv.y);
                __nv_bfloat16* dh0 = Chi + (long)z * sQ + (long)r0 * ldq + col;
                *reinterpret_cast<__nv_bfloat162*>(dh0) = p0;
                *reinterpret_cast<__nv_bfloat162*>(dh0 + 8 * ldq) = p1;
            }
        }
    }
}

// ---------------------------------------------------------------------------
// Per-batch mask prefix scan: qvalid (packed->orig) and Lv.
// ---------------------------------------------------------------------------
__global__ void mask_scan(const int* __restrict__ qm,
                          int* __restrict__ qvalid, int* __restrict__ Lv)
{
    const int b = blockIdx.x, t = threadIdx.x;
    __shared__ int sc[256];
    const int* m = qm + (long)b * kLQ;
    int mv[4];
    #pragma unroll
    for (int i = 0; i < 4; i++) mv[i] = m[t * 4 + i];
    const int c = mv[0] + mv[1] + mv[2] + mv[3];
    sc[t] = c;
    __syncthreads();
    for (int off = 1; off < 256; off <<= 1) {
        const int v = (t >= off) ? sc[t - off] : 0;
        __syncthreads();
        sc[t] += v;
        __syncthreads();
    }
    int exc = sc[t] - c;
    int* qv = qvalid + (long)b * kLQ;
    #pragma unroll
    for (int i = 0; i < 4; i++) {
        const int q = t * 4 + i;
        if (mv[i]) { qv[exc] = q; exc++; }
    }
    if (t == 255) Lv[b] = sc[255];
}

// ---------------------------------------------------------------------------
// qh -> (a) packed bf16 rows [B, packed_q, D]   (K1's A operand)
//       (b) packed transposed [B, D, packed_q]  (K4's B operand)
// ---------------------------------------------------------------------------
__global__ void gather_pack(const float* __restrict__ in,
                            const int* __restrict__ qvalid,
                            const int* __restrict__ LvArr,
                            __nv_bfloat16* __restrict__ pk,
                            __nv_bfloat16* __restrict__ oT)
{
    const int b  = blockIdx.z;
    const int lv = __ldg(&LvArr[b]);
    const int q0 = blockIdx.y * 32;               // packed row tile
    if (q0 >= ((lv + 127) & ~127)) return;
    const int d0 = blockIdx.x * 32;
    const int tx = threadIdx.x, ty = threadIdx.y;

    __shared__ float t[32][33];
    __shared__ int src[32];
    if (ty == 0) {
        const int j = q0 + tx;
        src[tx] = (j < lv) ? __ldg(&qvalid[b * kLQ + j]) : -1;
    }
    __syncthreads();

    const float* ib = in + (long)b * kLQ * kD;
    __nv_bfloat16* pb = pk + (long)b * kLQ * kD;
    #pragma unroll
    for (int j = 0; j < 4; j++) {
        const int row = ty + 8 * j;               // packed row within tile
        const int sq  = src[row];
        const float v = (sq >= 0) ? ib[(long)sq * kD + d0 + tx] : 0.f;
        t[row][tx] = v;
        pb[(long)(q0 + row) * kD + d0 + tx] = __float2bfloat16(v);
    }
    __syncthreads();
    __nv_bfloat16* bh = oT + (long)b * kD * kLQ;
    #pragma unroll
    for (int j = 0; j < 4; j++) {
        const float v = t[tx][ty + 8 * j];
        bh[(long)(d0 + ty + 8 * j) * kLQ + q0 + tx] = __float2bfloat16(v);
    }
}

// ---------------------------------------------------------------------------
// ctx: one read -> output first half copy + bf16 convert
// ---------------------------------------------------------------------------
__global__ void prep_ctx(const float* __restrict__ ctx, float* __restrict__ out,
                         __nv_bfloat16* __restrict__ hi)
{
    const int n4 = kB * kLC * (kD / 4);
    const int i = blockIdx.x * blockDim.x + threadIdx.x;
    if (i >= n4) return;
    const float4 v = reinterpret_cast<const float4*>(ctx)[i];
    const int row = i / (kD / 4);
    const int col = i - row * (kD / 4);
    reinterpret_cast<float4*>(out)[(long)row * (2 * kD / 4) + col] = v;
    __nv_bfloat162 p0; p0.x = __float2bfloat16(v.x); p0.y = __float2bfloat16(v.y);
    __nv_bfloat162 p1; p1.x = __float2bfloat16(v.z); p1.y = __float2bfloat16(v.w);
    reinterpret_cast<__nv_bfloat162*>(hi)[2*i+0] = p0;
    reinterpret_cast<__nv_bfloat162*>(hi)[2*i+1] = p1;
}

// ---------------------------------------------------------------------------
// fp32 -> bf16 convert (W)
// ---------------------------------------------------------------------------
__global__ void split_hi(const float* __restrict__ in,
                         __nv_bfloat16* __restrict__ hi, int n4)
{
    const int i = blockIdx.x * blockDim.x + threadIdx.x;
    if (i >= n4) return;
    const float4 v = reinterpret_cast<const float4*>(in)[i];
    __nv_bfloat162 p0; p0.x = __float2bfloat16(v.x); p0.y = __float2bfloat16(v.y);
    __nv_bfloat162 p1; p1.x = __float2bfloat16(v.z); p1.y = __float2bfloat16(v.w);
    reinterpret_cast<__nv_bfloat162*>(hi)[2*i+0] = p0;
    reinterpret_cast<__nv_bfloat162*>(hi)[2*i+1] = p1;
}

// ---------------------------------------------------------------------------
// Softmax over packed columns [0, Lv); writes p_hi zeros in [Lv, pad128(Lv)).
// ---------------------------------------------------------------------------
__global__ void softmax_packed(const float* __restrict__ scores,
                               const int* __restrict__ LvArr,
                               __nv_bfloat16* __restrict__ phi)
{
    const int row = blockIdx.x;              // 0 .. B*LC-1
    const int b   = row >> 11;               // / kLC
    const int lv  = __ldg(&LvArr[b]);
    const int lim = (lv + 127) & ~127;
    const float* s = scores + (long)row * kLQ;

    const int t = threadIdx.x;               // 256 threads, 4 elems each
    float v[4]; int ok[4];
    float mx = -1e30f;
    #pragma unroll
    for (int i = 0; i < 4; i++) {
        const int q = t + i * 256;
        ok[i] = (q < lv);
        v[i]  = ok[i] ? s[q] : 0.f;
        if (ok[i]) mx = fmaxf(mx, v[i]);
    }

    __shared__ float smax[8];
    __shared__ float ssum[8];

    #pragma unroll
    for (int off = 16; off; off >>= 1)
        mx = fmaxf(mx, __shfl_xor_sync(0xffffffffu, mx, off));
    if ((t & 31) == 0) smax[t >> 5] = mx;
    __syncthreads();
    float bm = -1e30f;
    #pragma unroll
    for (int w = 0; w < 8; w++) bm = fmaxf(bm, smax[w]);

    float e[4];
    float sum = 0.f;
    #pragma unroll
    for (int i = 0; i < 4; i++) {
        e[i] = ok[i] ? __expf(v[i] - bm) : 0.f;
        sum += e[i];
    }
    #pragma unroll
    for (int off = 16; off; off >>= 1)
        sum += __shfl_xor_sync(0xffffffffu, sum, off);
    if ((t & 31) == 0) ssum[t >> 5] = sum;
    __syncthreads();
    float total = 0.f;
    #pragma unroll
    for (int w = 0; w < 8; w++) total += ssum[w];

    const float inv = 1.f / total;
    __nv_bfloat16* dh = phi + (long)row * kLQ;
    #pragma unroll
    for (int i = 0; i < 4; i++) {
        const int q = t + i * 256;
        if (q < lim) dh[q] = __float2bfloat16(e[i] * inv);   // 0 for q in [lv, lim)
    }
}

// ---------------------------------------------------------------------------
extern "C" void kernel_launch(void* const* d_in, const int* in_sizes, int n_in,
                              void* d_out, int out_size)
{
    const float* ctx  = (const float*)d_in[0];
    const float* qh   = (const float*)d_in[2];
    const int*   qm   = (const int*)d_in[3];
    const float* W    = (const float*)d_in[4];
    const float* bias = (const float*)d_in[5];
    float* out = (float*)d_out;
    (void)in_sizes; (void)n_in; (void)out_size;

    __nv_bfloat16 *ctx_hi, *qh_pk, *qhT_hi, *W_hi, *q_hi, *p_hi;
    float* scores;
    int *qvalid, *Lv;
    cudaGetSymbolAddress((void**)&ctx_hi, g_ctx_hi);
    cudaGetSymbolAddress((void**)&qh_pk,  g_qh_pk);
    cudaGetSymbolAddress((void**)&qhT_hi, g_qhT_hi);
    cudaGetSymbolAddress((void**)&W_hi,   g_W_hi);
    cudaGetSymbolAddress((void**)&q_hi,   g_q_hi);
    cudaGetSymbolAddress((void**)&p_hi,   g_p_hi);
    cudaGetSymbolAddress((void**)&scores, g_scores);
    cudaGetSymbolAddress((void**)&qvalid, g_qvalid);
    cudaGetSymbolAddress((void**)&Lv,     g_Lv);

    // One-time resource setup (first call is the uncaptured correctness run;
    // captured calls then only record/wait on these — pure graph nodes, no
    // resource creation inside capture, no leaks across replays).
    static cudaStream_t s1 = nullptr;
    static cudaEvent_t eFork = nullptr, eJoin = nullptr;
    if (s1 == nullptr) {
        cudaStreamCreateWithFlags(&s1, cudaStreamNonBlocking);
        cudaEventCreateWithFlags(&eFork, cudaEventDisableTiming);
        cudaEventCreateWithFlags(&eJoin, cudaEventDisableTiming);
        cudaFuncSetAttribute(gemm_tc<0>, cudaFuncAttributeMaxDynamicSharedMemorySize, SMEM_SZ);
        cudaFuncSetAttribute(gemm_tc<1>, cudaFuncAttributeMaxDynamicSharedMemorySize, SMEM_SZ);
        cudaFuncSetAttribute(gemm_tc<2>, cudaFuncAttributeMaxDynamicSharedMemorySize, SMEM_SZ);
    }

    // Fork: side stream runs the independent ctx branch.
    cudaEventRecord(eFork, 0);
    cudaStreamWaitEvent(s1, eFork, 0);

    // Branch B (stream s1): ctx copy + convert — HBM-bound, overlaps branch A.
    prep_ctx<<<(kB * kLC * (kD / 4) + 255) / 256, 256, 0, s1>>>(ctx, out, ctx_hi);
    cudaEventRecord(eJoin, s1);

    // Branch A (main stream): W convert, mask scan, qh gather/transpose, K1.
    split_hi<<<(kD * kD / 4 + 255) / 256, 256>>>(W, W_hi, kD * kD / 4);
    mask_scan<<<kB, 256>>>(qm, qvalid, Lv);
    gather_pack<<<dim3(kD / 32, kLQ / 32, kB), dim3(32, 8)>>>(qh, qvalid, Lv, qh_pk, qhT_hi);
    gemm_tc<0><<<dim3(kD / 128, kLQ / 128, kB), 256, SMEM_SZ>>>(
        qh_pk, (long)kLQ * kD, kD,
        W_hi, 0, kD, kD,
        nullptr, 0, 0, 0, 1.0f, bias,
        q_hi, (long)kLQ * kD, kD, Lv);

    // Join: K2 needs both ctx_hi (branch B) and q_hi (branch A).
    cudaStreamWaitEvent(0, eJoin, 0);

    // K2: packed scores = scale * ctx_hi @ q_hi^T (N-early-exit at Lv)
    gemm_tc<1><<<dim3(kLQ / 128, kLC / 128, kB), 256, SMEM_SZ>>>(
        ctx_hi, (long)kLC * kD, kD,
        q_hi, (long)kLQ * kD, kD, kD,
        scores, (long)kLC * kLQ, kLQ, 0, kScale, nullptr,
        nullptr, 0, 0, Lv);
    // softmax -> p_hi (zeros in pad region)
    softmax_packed<<<kB * kLC, 256>>>(scores, Lv, p_hi);
    // K4: out[:, D:] = p_hi @ qhT_hi^T (runtime K = pad128(Lv))
    gemm_tc<2><<<dim3(kD / 128, kLC / 128, kB), 256, SMEM_SZ>>>(
        p_hi, (long)kLC * kLQ, kLQ,
        qhT_hi, (long)kD * kLQ, kLQ, 0,
        out, (long)kLC * 2 * kD, 2 * kD, kD, 1.0f, nullptr,
        nullptr, 0, 0, Lv);
}